// round 8
// baseline (speedup 1.0000x reference)
#include <cuda_runtime.h>
#include <cuda_bf16.h>
#include <cstdint>

#define CC 32
#define TT 2048
#define EMB 1024
#define NH 16
#define DH 64
#define MAPD 4096
#define NROWS (CC*TT)          // 65536
#define EPS_LN 1e-5f

// ---------------- scratch (static device globals) ----------------
__device__ float g_M[DH*DH];
__device__ float g_xpart[512*EMB];
__device__ float g_vsum[CC*EMB];
__device__ float g_w[NROWS*NH];
// split-bf16 interleaved: row-major [rows][2*K], each 32-k block stored [hi(32)|lo(32)]
__device__ __align__(128) __nv_bfloat16 g_y2[(size_t)NROWS*(2*EMB)];    // 268 MB
__device__ __align__(128) __nv_bfloat16 g_h2[(size_t)NROWS*(2*MAPD)];   // 1.07 GB
__device__ __align__(128) __nv_bfloat16 g_w1[(size_t)MAPD*(2*EMB)];     // 16 MB
__device__ __align__(128) __nv_bfloat16 g_w2[(size_t)EMB*(2*MAPD)];     // 16 MB

// ---------------- helpers ----------------
__device__ __forceinline__ uint32_t smem_u32(const void* p){
    uint32_t a;
    asm("{ .reg .u64 t; cvta.to.shared.u64 t, %1; cvt.u32.u64 %0, t; }" : "=r"(a) : "l"(p));
    return a;
}
__device__ __forceinline__ void cp16(uint32_t dst, const void* src){
    asm volatile("cp.async.cg.shared.global [%0], [%1], 16;" :: "r"(dst), "l"(src) : "memory");
}
__device__ __forceinline__ void cp_commit(){ asm volatile("cp.async.commit_group;" ::: "memory"); }
__device__ __forceinline__ void cp_wait1(){ asm volatile("cp.async.wait_group 1;" ::: "memory"); }
__device__ __forceinline__ void cp_wait0(){ asm volatile("cp.async.wait_group 0;" ::: "memory"); }

__device__ __forceinline__ void ldm4(uint32_t a, uint32_t* r){
    asm volatile("ldmatrix.sync.aligned.m8n8.x4.shared.b16 {%0,%1,%2,%3}, [%4];"
        : "=r"(r[0]), "=r"(r[1]), "=r"(r[2]), "=r"(r[3]) : "r"(a));
}
__device__ __forceinline__ void mma16816(float* d, const uint32_t* a, uint32_t b0, uint32_t b1){
    asm volatile("mma.sync.aligned.m16n8k16.row.col.f32.bf16.bf16.f32 "
        "{%0,%1,%2,%3}, {%4,%5,%6,%7}, {%8,%9}, {%0,%1,%2,%3};"
        : "+f"(d[0]), "+f"(d[1]), "+f"(d[2]), "+f"(d[3])
        : "r"(a[0]), "r"(a[1]), "r"(a[2]), "r"(a[3]), "r"(b0), "r"(b1));
}

// ---------------- kernel 1: weight split + partial xsum + prep_M (fused) ----------------
__global__ void k_presplit(const float* __restrict__ inp,
                           const float* __restrict__ wq, const float* __restrict__ wk,
                           const float* __restrict__ w1src, const float* __restrict__ w2src,
                           __nv_bfloat16* __restrict__ d1, __nv_bfloat16* __restrict__ d2){
    int b = blockIdx.x, tid = threadIdx.x;
    if(b < 8192){
        const float* src; __nv_bfloat16* dst; int K; int i;
        if(b < 4096){ src = w1src; dst = d1; K = EMB;  i = b*256 + tid; }
        else        { src = w2src; dst = d2; K = MAPD; i = (b-4096)*256 + tid; }
        int base = i*4;
        int row = base / K, k = base % K;
        float4 v = *(const float4*)(src + base);
        float x[4] = {v.x, v.y, v.z, v.w};
        unsigned short hb[4], lb[4];
        #pragma unroll
        for(int u=0;u<4;u++){
            __nv_bfloat16 h = __float2bfloat16(x[u]);
            __nv_bfloat16 l = __float2bfloat16(x[u] - __bfloat162float(h));
            hb[u] = *(unsigned short*)&h;
            lb[u] = *(unsigned short*)&l;
        }
        __nv_bfloat16* d = dst + (size_t)row*(2*K) + (size_t)(k>>5)*64 + (k&31);
        *(uint2*)d      = make_uint2((uint32_t)hb[0] | ((uint32_t)hb[1]<<16),
                                     (uint32_t)hb[2] | ((uint32_t)hb[3]<<16));
        *(uint2*)(d+32) = make_uint2((uint32_t)lb[0] | ((uint32_t)lb[1]<<16),
                                     (uint32_t)lb[2] | ((uint32_t)lb[3]<<16));
        return;
    }
    if(b == 8704){
        __shared__ float sq[DH*DH], sk[DH*DH];
        for(int i=tid;i<DH*DH;i+=256){ sq[i]=wq[i]; sk[i]=wk[i]; }
        __syncthreads();
        for(int idx=tid; idx<DH*DH; idx+=256){
            int d = idx/DH, e = idx%DH;
            float s = 0.f;
            #pragma unroll
            for(int o=0;o<DH;o++) s += sq[o*DH+d]*sk[o*DH+e];
            g_M[idx] = s;
        }
        return;
    }
    int b2 = b - 8192;
    int c = b2>>4, seg = b2&15;
    size_t base = ((size_t)c*TT + (size_t)seg*128)*EMB;
    #pragma unroll
    for(int j=0;j<4;j++){
        int e = tid + j*256;
        float acc = 0.f;
        const float* p = inp + base + e;
        #pragma unroll 4
        for(int t=0;t<128;t++) acc += p[(size_t)t*EMB];
        g_xpart[(size_t)b2*EMB + e] = acc;
    }
}

// ---------------- kernel 2: diag scores + vsum ----------------
__global__ __launch_bounds__(256) void k_diagv(const float* __restrict__ inp,
                                               const float* __restrict__ wv){
    if(blockIdx.x >= 16384){
        int b2 = blockIdx.x - 16384;
        int c = b2>>4, h = b2&15;
        __shared__ float xs[DH];
        int tid = threadIdx.x;
        if(tid < DH){
            float s = 0.f;
            #pragma unroll
            for(int seg=0;seg<16;seg++) s += g_xpart[(size_t)(c*16+seg)*EMB + h*DH + tid];
            xs[tid] = s;
        }
        __syncthreads();
        if(tid < DH){
            float s = 0.f;
            #pragma unroll
            for(int d=0;d<DH;d++) s += xs[d]*wv[tid*DH+d];
            g_vsum[c*EMB + h*DH + tid] = s;
        }
        return;
    }
    __shared__ float Ms[DH][DH];
    __shared__ float Xs[64][DH+1];
    __shared__ float ds[64];
    int g0 = blockIdx.x*64;
    int tid = threadIdx.x, tx = tid&15, ty = tid>>4;
    for(int i=tid;i<DH*DH;i+=256) (&Ms[0][0])[i] = g_M[i];
    {
        const float* src = inp + (size_t)g0*DH;
        for(int i=tid;i<64*(DH/4);i+=256){
            int r = i/(DH/4), q = i%(DH/4);
            float4 v = *(const float4*)(src + (size_t)r*DH + q*4);
            Xs[r][q*4+0]=v.x; Xs[r][q*4+1]=v.y; Xs[r][q*4+2]=v.z; Xs[r][q*4+3]=v.w;
        }
    }
    __syncthreads();
    float acc[4][4] = {};
    #pragma unroll 8
    for(int k=0;k<DH;k++){
        float a[4], b[4];
        #pragma unroll
        for(int i=0;i<4;i++) a[i] = Xs[ty*4+i][k];
        #pragma unroll
        for(int j=0;j<4;j++) b[j] = Ms[k][tx*4+j];
        #pragma unroll
        for(int i=0;i<4;i++)
            #pragma unroll
            for(int j=0;j<4;j++) acc[i][j] += a[i]*b[j];
    }
    #pragma unroll
    for(int i=0;i<4;i++){
        float p = 0.f;
        #pragma unroll
        for(int j=0;j<4;j++) p += acc[i][j]*Xs[ty*4+i][tx*4+j];
        #pragma unroll
        for(int off=8;off;off>>=1) p += __shfl_down_sync(0xffffffffu, p, off, 16);
        if(tx==0) ds[ty*4+i] = p;
    }
    __syncthreads();
    if(tid < 64) g_w[g0+tid] = ds[tid]*(1.0f/32.0f);
}

// ---------------- block reduction ----------------
__device__ __forceinline__ float blk_reduce(float v, float* red){
    int lane = threadIdx.x&31, w = threadIdx.x>>5;
    #pragma unroll
    for(int off=16;off;off>>=1) v += __shfl_down_sync(0xffffffffu, v, off);
    if(lane==0) red[w] = v;
    __syncthreads();
    if(w==0){
        float x = (lane<8)? red[lane] : 0.f;
        #pragma unroll
        for(int off=4;off;off>>=1) x += __shfl_down_sync(0xffffffffu, x, off);
        if(lane==0) red[0] = x;
    }
    __syncthreads();
    float r = red[0];
    __syncthreads();
    return r;
}

// ---------------- kernel 3: softmax + residual + LN1, split-bf16 out ----------------
__global__ __launch_bounds__(256) void k_ln1(const float* __restrict__ inp,
                                             const float* __restrict__ g1,
                                             const float* __restrict__ b1){
    __shared__ float red[8];
    __shared__ float ws[NH];
    int row = blockIdx.x, c = row>>11, t = row&2047;
    int tid = threadIdx.x;
    if(tid < NH){
        int h = tid;
        size_t idx = (size_t)t*NH + h;
        float d[CC], m = -1e30f;
        #pragma unroll
        for(int c2=0;c2<CC;c2++){
            d[c2] = g_w[(size_t)c2*(TT*NH) + idx];
            m = fmaxf(m, d[c2]);
        }
        float s = 0.f;
        #pragma unroll
        for(int c2=0;c2<CC;c2++) s += __expf(d[c2]-m);
        ws[h] = __expf(d[c]-m) / s;
    }
    __syncthreads();
    float x[4]; float s = 0.f;
    #pragma unroll
    for(int j=0;j<4;j++){
        int e = tid + j*256;
        float v = inp[(size_t)row*EMB + e] + ws[e>>6]*g_vsum[c*EMB + e];
        x[j] = v; s += v;
    }
    float mu = blk_reduce(s, red)*(1.f/EMB);
    float q = 0.f;
    #pragma unroll
    for(int j=0;j<4;j++){ float d = x[j]-mu; q += d*d; }
    float rstd = rsqrtf(blk_reduce(q, red)*(1.f/EMB) + EPS_LN);
    #pragma unroll
    for(int j=0;j<4;j++){
        int e = tid + j*256;
        float val = x[j] + (x[j]-mu)*rstd*g1[e] + b1[e];
        __nv_bfloat16 hi = __float2bfloat16(val);
        __nv_bfloat16 lo = __float2bfloat16(val - __bfloat162float(hi));
        size_t base = (size_t)row*(2*EMB) + (size_t)(e>>5)*64 + (e&31);
        g_y2[base]    = hi;
        g_y2[base+32] = lo;
    }
}

// ---------------- final LN2 ----------------
__global__ __launch_bounds__(256) void k_ln2(float* __restrict__ out,
                                             const float* __restrict__ g2,
                                             const float* __restrict__ b2){
    __shared__ float red[8];
    int row = blockIdx.x;
    int tid = threadIdx.x;
    float x[4]; float s = 0.f;
    #pragma unroll
    for(int j=0;j<4;j++){
        int e = tid + j*256;
        x[j] = out[(size_t)row*EMB + e]; s += x[j];
    }
    float mu = blk_reduce(s, red)*(1.f/EMB);
    float q = 0.f;
    #pragma unroll
    for(int j=0;j<4;j++){ float d = x[j]-mu; q += d*d; }
    float rstd = rsqrtf(blk_reduce(q, red)*(1.f/EMB) + EPS_LN);
    #pragma unroll
    for(int j=0;j<4;j++){
        int e = tid + j*256;
        out[(size_t)row*EMB + e] = (x[j]-mu)*rstd*g2[e] + b2[e];
    }
}

// ---------------- split-bf16 warp-MMA GEMM ----------------
// CTA tile 128x256, 256 threads (8 warps 2Mx4N), warp tile 64x64.
// BK=32 real k (64 interleaved cols = 128B/row), 3-stage cp.async.
// acc 128 regs/thread; high-ILP CUTLASS-style shape.
#define STRIDE_B 144
#define STAGE_ROWS 384                 // 128 A rows + 256 B rows
#define STAGE_BYTES (STAGE_ROWS*STRIDE_B)  // 55296
#define GEMM_SMEM (3*STAGE_BYTES)          // 165888

template<int SPLIT_OUT>
__global__ __launch_bounds__(256, 1) void k_gemm_mma(
    const __nv_bfloat16* __restrict__ A,
    const __nv_bfloat16* __restrict__ B,
    const float* __restrict__ bias,
    float* __restrict__ Cf,
    __nv_bfloat16* __restrict__ Cs,
    int K2, int Nfull)
{
    extern __shared__ char smem_raw[];
    const uint32_t sb = smem_u32(smem_raw);
    const int tid = threadIdx.x;
    const int wid = tid >> 5, lane = tid & 31;
    const int wm = wid & 1, wn = wid >> 1;   // 2 x 4 warp grid, warp tile 64x64

    const size_t bm = (size_t)blockIdx.y * 128;
    const size_t bn = (size_t)blockIdx.x * 256;
    const int NKC = K2 >> 6;

    const char* Ag = (const char*)(A + bm * (size_t)K2);
    const char* Bg = (const char*)(B + bn * (size_t)K2);
    const size_t rstride = (size_t)K2 * 2;

    const int ldr = tid >> 3;          // 0..31
    const int ldc = (tid & 7) << 4;

    auto load_stage = [&](int kc){
        uint32_t st = sb + (kc%3)*STAGE_BYTES;
        size_t gofs = (size_t)kc*128;
        #pragma unroll
        for(int i=0;i<12;i++){
            int r = ldr + i*32;
            if (r < 128)
                cp16(st + r*STRIDE_B + ldc, Ag + (size_t)r*rstride + gofs + ldc);
            else
                cp16(st + r*STRIDE_B + ldc, Bg + (size_t)(r-128)*rstride + gofs + ldc);
        }
        cp_commit();
    };

    float acc[4][8][4];
    #pragma unroll
    for(int i=0;i<4;i++)
        #pragma unroll
        for(int j=0;j<8;j++)
            #pragma unroll
            for(int q=0;q<4;q++) acc[i][j][q] = 0.f;

    load_stage(0); load_stage(1);

    const uint32_t lrow = lane & 15;
    const uint32_t lcol = (lane >> 4) << 4;

    for(int kc=0; kc<NKC; kc++){
        cp_wait1();
        __syncthreads();
        if (kc+2 < NKC) load_stage(kc+2);

        uint32_t sA = sb + (kc%3)*STAGE_BYTES;
        uint32_t sB = sA + 128*STRIDE_B;
        uint32_t aBase = sA + (wm*64 + lrow)*STRIDE_B + lcol;
        uint32_t bBase = sB + (wn*64 + lrow)*STRIDE_B + lcol;

        #pragma unroll
        for(int s=0;s<2;s++){
            uint32_t af[2][4][4];   // [prec][mtile 0..3]
            uint32_t bf[2][4][4];   // [prec][ntile16 0..3]
            #pragma unroll
            for(int p=0;p<2;p++)
                #pragma unroll
                for(int i=0;i<4;i++)
                    ldm4(aBase + i*16*STRIDE_B + (p*64 + s*32), af[p][i]);
            #pragma unroll
            for(int p=0;p<2;p++)
                #pragma unroll
                for(int j=0;j<4;j++)
                    ldm4(bBase + j*16*STRIDE_B + (p*64 + s*32), bf[p][j]);

            #pragma unroll
            for(int pass=0;pass<3;pass++){
                const int pa = (pass==2) ? 1 : 0;
                const int pb = (pass==1) ? 1 : 0;
                #pragma unroll
                for(int i=0;i<4;i++){
                    #pragma unroll
                    for(int j=0;j<4;j++){
                        mma16816(acc[i][2*j],   af[pa][i], bf[pb][j][0], bf[pb][j][2]);
                        mma16816(acc[i][2*j+1], af[pa][i], bf[pb][j][1], bf[pb][j][3]);
                    }
                }
            }
        }
    }
    cp_wait0();

    // epilogue
    const int r4 = lane >> 2, c2 = (lane & 3) << 1;
    #pragma unroll
    for(int i=0;i<4;i++){
        size_t row0 = bm + wm*64 + i*16 + r4;
        #pragma unroll
        for(int j=0;j<8;j++){
            size_t n0 = bn + wn*64 + j*8 + c2;
            float b0 = bias[n0], b1 = bias[n0+1];
            float v00 = acc[i][j][0] + b0, v01 = acc[i][j][1] + b1;
            float v10 = acc[i][j][2] + b0, v11 = acc[i][j][3] + b1;
            if (SPLIT_OUT){
                size_t off = (size_t)(n0>>5)*64 + (n0&31);
                __nv_bfloat16* d0 = Cs + row0*(size_t)(2*Nfull) + off;
                __nv_bfloat16* d1 = Cs + (row0+8)*(size_t)(2*Nfull) + off;
                __nv_bfloat16 h00 = __float2bfloat16(v00), h01 = __float2bfloat16(v01);
                __nv_bfloat16 h10 = __float2bfloat16(v10), h11 = __float2bfloat16(v11);
                __nv_bfloat16 l00 = __float2bfloat16(v00 - __bfloat162float(h00));
                __nv_bfloat16 l01 = __float2bfloat16(v01 - __bfloat162float(h01));
                __nv_bfloat16 l10 = __float2bfloat16(v10 - __bfloat162float(h10));
                __nv_bfloat16 l11 = __float2bfloat16(v11 - __bfloat162float(h11));
                *(uint32_t*)d0      = (uint32_t)(*(unsigned short*)&h00) | ((uint32_t)(*(unsigned short*)&h01)<<16);
                *(uint32_t*)(d0+32) = (uint32_t)(*(unsigned short*)&l00) | ((uint32_t)(*(unsigned short*)&l01)<<16);
                *(uint32_t*)d1      = (uint32_t)(*(unsigned short*)&h10) | ((uint32_t)(*(unsigned short*)&h11)<<16);
                *(uint32_t*)(d1+32) = (uint32_t)(*(unsigned short*)&l10) | ((uint32_t)(*(unsigned short*)&l11)<<16);
            } else {
                float* d0 = Cf + row0*(size_t)Nfull + n0;
                float* d1 = Cf + (row0+8)*(size_t)Nfull + n0;
                d0[0] = v00; d0[1] = v01;
                d1[0] = v10; d1[1] = v11;
            }
        }
    }
}

// ---------------- launch ----------------
extern "C" void kernel_launch(void* const* d_in, const int* in_sizes, int n_in,
                              void* d_out, int out_size){
    const float* inp   = (const float*)d_in[0];
    const float* wq    = (const float*)d_in[1];
    const float* wk    = (const float*)d_in[2];
    const float* wv    = (const float*)d_in[3];
    const float* ln1_g = (const float*)d_in[4];
    const float* ln1_b = (const float*)d_in[5];
    const float* fc1_w = (const float*)d_in[6];
    const float* fc1_b = (const float*)d_in[7];
    const float* fc2_w = (const float*)d_in[8];
    const float* fc2_b = (const float*)d_in[9];
    const float* ln2_g = (const float*)d_in[10];
    const float* ln2_b = (const float*)d_in[11];
    float* out = (float*)d_out;

    __nv_bfloat16 *y2p=nullptr, *h2p=nullptr, *w1p=nullptr, *w2p=nullptr;
    cudaGetSymbolAddress((void**)&y2p, g_y2);
    cudaGetSymbolAddress((void**)&h2p, g_h2);
    cudaGetSymbolAddress((void**)&w1p, g_w1);
    cudaGetSymbolAddress((void**)&w2p, g_w2);

    cudaFuncSetAttribute(k_gemm_mma<1>, cudaFuncAttributeMaxDynamicSharedMemorySize, GEMM_SMEM);
    cudaFuncSetAttribute(k_gemm_mma<0>, cudaFuncAttributeMaxDynamicSharedMemorySize, GEMM_SMEM);

    // launch 1: weight split + xsum partials + prep_M (fused)
    k_presplit<<<8705, 256>>>(inp, wq, wk, fc1_w, fc2_w, w1p, w2p);
    // launch 2
    k_diagv<<<16384+512, 256>>>(inp, wv);
    // launch 3
    k_ln1<<<NROWS, 256>>>(inp, ln1_g, ln1_b);

    // launch 4: h = y @ fc1_w^T + b1 (split-bf16 out) — ncu profiles my launch #4
    k_gemm_mma<1><<<dim3(MAPD/256, NROWS/128), 256, GEMM_SMEM>>>(
        y2p, w1p, fc1_b, nullptr, h2p, 2*EMB, MAPD);
    // launch 5: out = h @ fc2_w^T + b2 (fp32 out)
    k_gemm_mma<0><<<dim3(EMB/256, NROWS/128), 256, GEMM_SMEM>>>(
        h2p, w2p, fc2_b, out, nullptr, 2*MAPD, EMB);

    k_ln2<<<NROWS, 256>>>(out, ln2_g, ln2_b);
}

// round 9
// speedup vs baseline: 1.5301x; 1.5301x over previous
#include <cuda_runtime.h>
#include <cuda_bf16.h>
#include <cuda_fp16.h>
#include <cstdint>

#define CC 32
#define TT 2048
#define EMB 1024
#define NH 16
#define DH 64
#define MAPD 4096
#define NROWS (CC*TT)          // 65536
#define EPS_LN 1e-5f

// ---------------- scratch (static device globals) ----------------
__device__ float g_M[DH*DH];
__device__ float g_xpart[512*EMB];
__device__ float g_vsum[CC*EMB];
__device__ float g_w[NROWS*NH];
// activations: plain fp16 (hi only). weights: interleaved [hi32|lo32] fp16.
__device__ __align__(128) __half g_y1[(size_t)NROWS*EMB];      // 134 MB
__device__ __align__(128) __half g_h1[(size_t)NROWS*MAPD];     // 536 MB
__device__ __align__(128) __half g_w1[(size_t)MAPD*(2*EMB)];   // 16 MB
__device__ __align__(128) __half g_w2[(size_t)EMB*(2*MAPD)];   // 16 MB

// ---------------- helpers ----------------
__device__ __forceinline__ uint32_t smem_u32(const void* p){
    uint32_t a;
    asm("{ .reg .u64 t; cvta.to.shared.u64 t, %1; cvt.u32.u64 %0, t; }" : "=r"(a) : "l"(p));
    return a;
}
__device__ __forceinline__ void cp16(uint32_t dst, const void* src){
    asm volatile("cp.async.cg.shared.global [%0], [%1], 16;" :: "r"(dst), "l"(src) : "memory");
}
__device__ __forceinline__ void cp_commit(){ asm volatile("cp.async.commit_group;" ::: "memory"); }
__device__ __forceinline__ void cp_wait1(){ asm volatile("cp.async.wait_group 1;" ::: "memory"); }
__device__ __forceinline__ void cp_wait0(){ asm volatile("cp.async.wait_group 0;" ::: "memory"); }

__device__ __forceinline__ void ldm4(uint32_t a, uint32_t* r){
    asm volatile("ldmatrix.sync.aligned.m8n8.x4.shared.b16 {%0,%1,%2,%3}, [%4];"
        : "=r"(r[0]), "=r"(r[1]), "=r"(r[2]), "=r"(r[3]) : "r"(a));
}
__device__ __forceinline__ void mma16816(float* d, const uint32_t* a, uint32_t b0, uint32_t b1){
    asm volatile("mma.sync.aligned.m16n8k16.row.col.f32.f16.f16.f32 "
        "{%0,%1,%2,%3}, {%4,%5,%6,%7}, {%8,%9}, {%0,%1,%2,%3};"
        : "+f"(d[0]), "+f"(d[1]), "+f"(d[2]), "+f"(d[3])
        : "r"(a[0]), "r"(a[1]), "r"(a[2]), "r"(a[3]), "r"(b0), "r"(b1));
}
__device__ __forceinline__ uint32_t packh(__half a, __half b){
    return (uint32_t)(*(unsigned short*)&a) | ((uint32_t)(*(unsigned short*)&b) << 16);
}

// ---------------- kernel 1: weight split (fp16) + partial xsum + prep_M ----------------
__global__ void k_presplit(const float* __restrict__ inp,
                           const float* __restrict__ wq, const float* __restrict__ wk,
                           const float* __restrict__ w1src, const float* __restrict__ w2src,
                           __half* __restrict__ d1, __half* __restrict__ d2){
    int b = blockIdx.x, tid = threadIdx.x;
    if(b < 8192){
        const float* src; __half* dst; int K; int i;
        if(b < 4096){ src = w1src; dst = d1; K = EMB;  i = b*256 + tid; }
        else        { src = w2src; dst = d2; K = MAPD; i = (b-4096)*256 + tid; }
        int base = i*4;
        int row = base / K, k = base % K;
        float4 v = *(const float4*)(src + base);
        float x[4] = {v.x, v.y, v.z, v.w};
        __half hb[4], lb[4];
        #pragma unroll
        for(int u=0;u<4;u++){
            hb[u] = __float2half_rn(x[u]);
            lb[u] = __float2half_rn(x[u] - __half2float(hb[u]));
        }
        __half* d = dst + (size_t)row*(2*K) + (size_t)(k>>5)*64 + (k&31);
        *(uint2*)d      = make_uint2(packh(hb[0],hb[1]), packh(hb[2],hb[3]));
        *(uint2*)(d+32) = make_uint2(packh(lb[0],lb[1]), packh(lb[2],lb[3]));
        return;
    }
    if(b == 8704){
        __shared__ float sq[DH*DH], sk[DH*DH];
        for(int i=tid;i<DH*DH;i+=256){ sq[i]=wq[i]; sk[i]=wk[i]; }
        __syncthreads();
        for(int idx=tid; idx<DH*DH; idx+=256){
            int d = idx/DH, e = idx%DH;
            float s = 0.f;
            #pragma unroll
            for(int o=0;o<DH;o++) s += sq[o*DH+d]*sk[o*DH+e];
            g_M[idx] = s;
        }
        return;
    }
    int b2 = b - 8192;
    int c = b2>>4, seg = b2&15;
    size_t base = ((size_t)c*TT + (size_t)seg*128)*EMB;
    #pragma unroll
    for(int j=0;j<4;j++){
        int e = tid + j*256;
        float acc = 0.f;
        const float* p = inp + base + e;
        #pragma unroll 4
        for(int t=0;t<128;t++) acc += p[(size_t)t*EMB];
        g_xpart[(size_t)b2*EMB + e] = acc;
    }
}

// ---------------- kernel 2: diag scores + vsum ----------------
__global__ __launch_bounds__(256) void k_diagv(const float* __restrict__ inp,
                                               const float* __restrict__ wv){
    if(blockIdx.x >= 16384){
        int b2 = blockIdx.x - 16384;
        int c = b2>>4, h = b2&15;
        __shared__ float xs[DH];
        int tid = threadIdx.x;
        if(tid < DH){
            float s = 0.f;
            #pragma unroll
            for(int seg=0;seg<16;seg++) s += g_xpart[(size_t)(c*16+seg)*EMB + h*DH + tid];
            xs[tid] = s;
        }
        __syncthreads();
        if(tid < DH){
            float s = 0.f;
            #pragma unroll
            for(int d=0;d<DH;d++) s += xs[d]*wv[tid*DH+d];
            g_vsum[c*EMB + h*DH + tid] = s;
        }
        return;
    }
    __shared__ float Ms[DH][DH];
    __shared__ float Xs[64][DH+1];
    __shared__ float ds[64];
    int g0 = blockIdx.x*64;
    int tid = threadIdx.x, tx = tid&15, ty = tid>>4;
    for(int i=tid;i<DH*DH;i+=256) (&Ms[0][0])[i] = g_M[i];
    {
        const float* src = inp + (size_t)g0*DH;
        for(int i=tid;i<64*(DH/4);i+=256){
            int r = i/(DH/4), q = i%(DH/4);
            float4 v = *(const float4*)(src + (size_t)r*DH + q*4);
            Xs[r][q*4+0]=v.x; Xs[r][q*4+1]=v.y; Xs[r][q*4+2]=v.z; Xs[r][q*4+3]=v.w;
        }
    }
    __syncthreads();
    float acc[4][4] = {};
    #pragma unroll 8
    for(int k=0;k<DH;k++){
        float a[4], b[4];
        #pragma unroll
        for(int i=0;i<4;i++) a[i] = Xs[ty*4+i][k];
        #pragma unroll
        for(int j=0;j<4;j++) b[j] = Ms[k][tx*4+j];
        #pragma unroll
        for(int i=0;i<4;i++)
            #pragma unroll
            for(int j=0;j<4;j++) acc[i][j] += a[i]*b[j];
    }
    #pragma unroll
    for(int i=0;i<4;i++){
        float p = 0.f;
        #pragma unroll
        for(int j=0;j<4;j++) p += acc[i][j]*Xs[ty*4+i][tx*4+j];
        #pragma unroll
        for(int off=8;off;off>>=1) p += __shfl_down_sync(0xffffffffu, p, off, 16);
        if(tx==0) ds[ty*4+i] = p;
    }
    __syncthreads();
    if(tid < 64) g_w[g0+tid] = ds[tid]*(1.0f/32.0f);
}

// ---------------- block reduction ----------------
__device__ __forceinline__ float blk_reduce(float v, float* red){
    int lane = threadIdx.x&31, w = threadIdx.x>>5;
    #pragma unroll
    for(int off=16;off;off>>=1) v += __shfl_down_sync(0xffffffffu, v, off);
    if(lane==0) red[w] = v;
    __syncthreads();
    if(w==0){
        float x = (lane<8)? red[lane] : 0.f;
        #pragma unroll
        for(int off=4;off;off>>=1) x += __shfl_down_sync(0xffffffffu, x, off);
        if(lane==0) red[0] = x;
    }
    __syncthreads();
    float r = red[0];
    __syncthreads();
    return r;
}

// ---------------- kernel 3: softmax + residual + LN1, fp16 out ----------------
__global__ __launch_bounds__(256) void k_ln1(const float* __restrict__ inp,
                                             const float* __restrict__ g1,
                                             const float* __restrict__ b1){
    __shared__ float red[8];
    __shared__ float ws[NH];
    int row = blockIdx.x, c = row>>11, t = row&2047;
    int tid = threadIdx.x;
    if(tid < NH){
        int h = tid;
        size_t idx = (size_t)t*NH + h;
        float d[CC], m = -1e30f;
        #pragma unroll
        for(int c2=0;c2<CC;c2++){
            d[c2] = g_w[(size_t)c2*(TT*NH) + idx];
            m = fmaxf(m, d[c2]);
        }
        float s = 0.f;
        #pragma unroll
        for(int c2=0;c2<CC;c2++) s += __expf(d[c2]-m);
        ws[h] = __expf(d[c]-m) / s;
    }
    __syncthreads();
    float x[4]; float s = 0.f;
    #pragma unroll
    for(int j=0;j<4;j++){
        int e = tid + j*256;
        float v = inp[(size_t)row*EMB + e] + ws[e>>6]*g_vsum[c*EMB + e];
        x[j] = v; s += v;
    }
    float mu = blk_reduce(s, red)*(1.f/EMB);
    float q = 0.f;
    #pragma unroll
    for(int j=0;j<4;j++){ float d = x[j]-mu; q += d*d; }
    float rstd = rsqrtf(blk_reduce(q, red)*(1.f/EMB) + EPS_LN);
    #pragma unroll
    for(int j=0;j<4;j++){
        int e = tid + j*256;
        float val = x[j] + (x[j]-mu)*rstd*g1[e] + b1[e];
        g_y1[(size_t)row*EMB + e] = __float2half_rn(val);
    }
}

// ---------------- final LN2 ----------------
__global__ __launch_bounds__(256) void k_ln2(float* __restrict__ out,
                                             const float* __restrict__ g2,
                                             const float* __restrict__ b2){
    __shared__ float red[8];
    int row = blockIdx.x;
    int tid = threadIdx.x;
    float x[4]; float s = 0.f;
    #pragma unroll
    for(int j=0;j<4;j++){
        int e = tid + j*256;
        x[j] = out[(size_t)row*EMB + e]; s += x[j];
    }
    float mu = blk_reduce(s, red)*(1.f/EMB);
    float q = 0.f;
    #pragma unroll
    for(int j=0;j<4;j++){ float d = x[j]-mu; q += d*d; }
    float rstd = rsqrtf(blk_reduce(q, red)*(1.f/EMB) + EPS_LN);
    #pragma unroll
    for(int j=0;j<4;j++){
        int e = tid + j*256;
        out[(size_t)row*EMB + e] = (x[j]-mu)*rstd*g2[e] + b2[e];
    }
}

// ---------------- fp16 2-pass warp-MMA GEMM ----------------
// C[M,N] = A[M,K] @ B[N,K]^T + bias.  A: plain fp16 [M][K].
// B: interleaved fp16 [N][2K] ([hi32|lo32] per 32-k block).
// acc = A*B_hi + A*B_lo (exact B; A's fp16 rounding is the only dropped term).
// CTA 128x128, 256 thr (8 warps 4Mx2N, warp 32x64), BK=32, 3-stage, 2 CTAs/SM.
#define A_STRIDE 80                    // 64B data + 16 pad (conflict-free)
#define B_STRIDE 144                   // 128B data + 16 pad
#define A_BYTES (128*A_STRIDE)         // 10240
#define STAGE_BYTES (A_BYTES + 128*B_STRIDE)   // 28672
#define GEMM_SMEM (3*STAGE_BYTES)              // 86016

template<int SPLIT_OUT>
__global__ __launch_bounds__(256, 2) void k_gemm_mma(
    const __half* __restrict__ A,
    const __half* __restrict__ B,
    const float* __restrict__ bias,
    float* __restrict__ Cf,
    __half* __restrict__ Cs,
    int Ka, int Nfull)
{
    extern __shared__ char smem_raw[];
    const uint32_t sb = smem_u32(smem_raw);
    const int tid = threadIdx.x;
    const int wid = tid >> 5, lane = tid & 31;
    const int wm = wid & 3, wn = wid >> 2;   // 4 x 2 warp grid, warp tile 32x64

    const size_t bm = (size_t)blockIdx.y * 128;
    const size_t bn = (size_t)blockIdx.x * 128;
    const int NKC = Ka >> 5;                 // 32 real k per chunk

    const char* Ag = (const char*)(A + bm * (size_t)Ka);
    const char* Bg = (const char*)(B + bn * (size_t)(2*Ka));
    const size_t rA = (size_t)Ka * 2;
    const size_t rB = (size_t)Ka * 4;

    auto load_stage = [&](int kc){
        uint32_t st = sb + (kc%3)*STAGE_BYTES;
        // A: 128 rows x 64B
        #pragma unroll
        for(int i=0;i<2;i++){
            int idx = tid + i*256;
            int r = idx >> 2, cs = (idx & 3) << 4;
            cp16(st + r*A_STRIDE + cs, Ag + (size_t)r*rA + (size_t)kc*64 + cs);
        }
        // B: 128 rows x 128B
        #pragma unroll
        for(int i=0;i<4;i++){
            int idx = tid + i*256;
            int r = idx >> 3, cs = (idx & 7) << 4;
            cp16(st + A_BYTES + r*B_STRIDE + cs, Bg + (size_t)r*rB + (size_t)kc*128 + cs);
        }
        cp_commit();
    };

    float acc[2][8][4];
    #pragma unroll
    for(int i=0;i<2;i++)
        #pragma unroll
        for(int j=0;j<8;j++)
            #pragma unroll
            for(int q=0;q<4;q++) acc[i][j][q] = 0.f;

    load_stage(0); load_stage(1);

    const uint32_t lrow = lane & 15;
    const uint32_t lcol = (lane >> 4) << 4;

    for(int kc=0; kc<NKC; kc++){
        cp_wait1();
        __syncthreads();
        if (kc+2 < NKC) load_stage(kc+2);

        uint32_t sA = sb + (kc%3)*STAGE_BYTES;
        uint32_t sB = sA + A_BYTES;
        uint32_t aBase = sA + (wm*32 + lrow)*A_STRIDE + lcol;
        uint32_t bBase = sB + (wn*64 + lrow)*B_STRIDE + lcol;

        #pragma unroll
        for(int s=0;s<2;s++){          // two k16 steps per chunk
            uint32_t af[2][4];         // [mtile]
            uint32_t bf[2][4][4];      // [prec hi/lo][ntile16]
            #pragma unroll
            for(int i=0;i<2;i++)
                ldm4(aBase + i*16*A_STRIDE + s*32, af[i]);
            #pragma unroll
            for(int p=0;p<2;p++)
                #pragma unroll
                for(int j=0;j<4;j++)
                    ldm4(bBase + j*16*B_STRIDE + (p*64 + s*32), bf[p][j]);

            #pragma unroll
            for(int p=0;p<2;p++){      // pass over B hi, then B lo
                #pragma unroll
                for(int i=0;i<2;i++){
                    #pragma unroll
                    for(int j=0;j<4;j++){
                        mma16816(acc[i][2*j],   af[i], bf[p][j][0], bf[p][j][2]);
                        mma16816(acc[i][2*j+1], af[i], bf[p][j][1], bf[p][j][3]);
                    }
                }
            }
        }
    }
    cp_wait0();

    // epilogue
    const int r4 = lane >> 2, c2 = (lane & 3) << 1;
    #pragma unroll
    for(int i=0;i<2;i++){
        size_t row0 = bm + wm*32 + i*16 + r4;
        #pragma unroll
        for(int j=0;j<8;j++){
            size_t n0 = bn + wn*64 + j*8 + c2;
            float b0 = bias[n0], b1 = bias[n0+1];
            float v00 = acc[i][j][0] + b0, v01 = acc[i][j][1] + b1;
            float v10 = acc[i][j][2] + b0, v11 = acc[i][j][3] + b1;
            if (SPLIT_OUT){
                *(uint32_t*)(Cs + row0*(size_t)Nfull + n0) =
                    packh(__float2half_rn(v00), __float2half_rn(v01));
                *(uint32_t*)(Cs + (row0+8)*(size_t)Nfull + n0) =
                    packh(__float2half_rn(v10), __float2half_rn(v11));
            } else {
                float* d0 = Cf + row0*(size_t)Nfull + n0;
                float* d1 = Cf + (row0+8)*(size_t)Nfull + n0;
                d0[0] = v00; d0[1] = v01;
                d1[0] = v10; d1[1] = v11;
            }
        }
    }
}

// ---------------- launch ----------------
extern "C" void kernel_launch(void* const* d_in, const int* in_sizes, int n_in,
                              void* d_out, int out_size){
    const float* inp   = (const float*)d_in[0];
    const float* wq    = (const float*)d_in[1];
    const float* wk    = (const float*)d_in[2];
    const float* wv    = (const float*)d_in[3];
    const float* ln1_g = (const float*)d_in[4];
    const float* ln1_b = (const float*)d_in[5];
    const float* fc1_w = (const float*)d_in[6];
    const float* fc1_b = (const float*)d_in[7];
    const float* fc2_w = (const float*)d_in[8];
    const float* fc2_b = (const float*)d_in[9];
    const float* ln2_g = (const float*)d_in[10];
    const float* ln2_b = (const float*)d_in[11];
    float* out = (float*)d_out;

    __half *y1p=nullptr, *h1p=nullptr, *w1p=nullptr, *w2p=nullptr;
    cudaGetSymbolAddress((void**)&y1p, g_y1);
    cudaGetSymbolAddress((void**)&h1p, g_h1);
    cudaGetSymbolAddress((void**)&w1p, g_w1);
    cudaGetSymbolAddress((void**)&w2p, g_w2);

    cudaFuncSetAttribute(k_gemm_mma<1>, cudaFuncAttributeMaxDynamicSharedMemorySize, GEMM_SMEM);
    cudaFuncSetAttribute(k_gemm_mma<0>, cudaFuncAttributeMaxDynamicSharedMemorySize, GEMM_SMEM);

    // launch 1: weight split (fp16) + xsum partials + prep_M
    k_presplit<<<8705, 256>>>(inp, wq, wk, fc1_w, fc2_w, w1p, w2p);
    // launch 2
    k_diagv<<<16384+512, 256>>>(inp, wv);
    // launch 3
    k_ln1<<<NROWS, 256>>>(inp, ln1_g, ln1_b);

    // launch 4: h = y @ fc1_w^T + b1 (fp16 out) — ncu slot
    k_gemm_mma<1><<<dim3(MAPD/128, NROWS/128), 256, GEMM_SMEM>>>(
        y1p, w1p, fc1_b, nullptr, h1p, EMB, MAPD);
    // launch 5: out = h @ fc2_w^T + b2 (fp32 out)
    k_gemm_mma<0><<<dim3(EMB/128, NROWS/128), 256, GEMM_SMEM>>>(
        h1p, w2p, fc2_b, out, nullptr, MAPD, EMB);

    k_ln2<<<NROWS, 256>>>(out, ln2_g, ln2_b);
}

// round 10
// speedup vs baseline: 2.3893x; 1.5615x over previous
#include <cuda_runtime.h>
#include <cuda_bf16.h>
#include <cuda_fp16.h>
#include <cstdint>

#define CC 32
#define TT 2048
#define EMB 1024
#define NH 16
#define DH 64
#define MAPD 4096
#define NROWS (CC*TT)          // 65536
#define EPS_LN 1e-5f

// ---------------- scratch (static device globals) ----------------
__device__ float g_M[DH*DH];
__device__ float g_xpart[512*EMB];
__device__ float g_vsum[CC*EMB];
__device__ float g_w[NROWS*NH];
// everything plain fp16 row-major
__device__ __align__(128) __half g_y1[(size_t)NROWS*EMB];      // 134 MB
__device__ __align__(128) __half g_h1[(size_t)NROWS*MAPD];     // 536 MB
__device__ __align__(128) __half g_w1[(size_t)MAPD*EMB];       // 8 MB
__device__ __align__(128) __half g_w2[(size_t)EMB*MAPD];       // 8 MB

// ---------------- helpers ----------------
__device__ __forceinline__ uint32_t smem_u32(const void* p){
    uint32_t a;
    asm("{ .reg .u64 t; cvta.to.shared.u64 t, %1; cvt.u32.u64 %0, t; }" : "=r"(a) : "l"(p));
    return a;
}
__device__ __forceinline__ void cp16(uint32_t dst, const void* src){
    asm volatile("cp.async.cg.shared.global [%0], [%1], 16;" :: "r"(dst), "l"(src) : "memory");
}
__device__ __forceinline__ void cp_commit(){ asm volatile("cp.async.commit_group;" ::: "memory"); }
__device__ __forceinline__ void cp_wait1(){ asm volatile("cp.async.wait_group 1;" ::: "memory"); }
__device__ __forceinline__ void cp_wait0(){ asm volatile("cp.async.wait_group 0;" ::: "memory"); }

__device__ __forceinline__ void ldm4(uint32_t a, uint32_t* r){
    asm volatile("ldmatrix.sync.aligned.m8n8.x4.shared.b16 {%0,%1,%2,%3}, [%4];"
        : "=r"(r[0]), "=r"(r[1]), "=r"(r[2]), "=r"(r[3]) : "r"(a));
}
__device__ __forceinline__ void mma16816(float* d, const uint32_t* a, uint32_t b0, uint32_t b1){
    asm volatile("mma.sync.aligned.m16n8k16.row.col.f32.f16.f16.f32 "
        "{%0,%1,%2,%3}, {%4,%5,%6,%7}, {%8,%9}, {%0,%1,%2,%3};"
        : "+f"(d[0]), "+f"(d[1]), "+f"(d[2]), "+f"(d[3])
        : "r"(a[0]), "r"(a[1]), "r"(a[2]), "r"(a[3]), "r"(b0), "r"(b1));
}
__device__ __forceinline__ uint32_t packh(__half a, __half b){
    return (uint32_t)(*(unsigned short*)&a) | ((uint32_t)(*(unsigned short*)&b) << 16);
}

// ---------------- kernel 1: weight fp16 cast + partial xsum + prep_M ----------------
// blocks [0,4096): w1 cast, [4096,8192): w2 cast, [8192,8704): xsum, 8704: prep_M
__global__ void k_presplit(const float* __restrict__ inp,
                           const float* __restrict__ wq, const float* __restrict__ wk,
                           const float* __restrict__ w1src, const float* __restrict__ w2src,
                           __half* __restrict__ d1, __half* __restrict__ d2){
    int b = blockIdx.x, tid = threadIdx.x;
    if(b < 8192){
        const float* src; __half* dst; int i;
        if(b < 4096){ src = w1src; dst = d1; i = b*256 + tid; }
        else        { src = w2src; dst = d2; i = (b-4096)*256 + tid; }
        int base = i*4;
        float4 v = *(const float4*)(src + base);
        *(uint2*)(dst + base) = make_uint2(
            packh(__float2half_rn(v.x), __float2half_rn(v.y)),
            packh(__float2half_rn(v.z), __float2half_rn(v.w)));
        return;
    }
    if(b == 8704){
        __shared__ float sq[DH*DH], sk[DH*DH];
        for(int i=tid;i<DH*DH;i+=256){ sq[i]=wq[i]; sk[i]=wk[i]; }
        __syncthreads();
        for(int idx=tid; idx<DH*DH; idx+=256){
            int d = idx/DH, e = idx%DH;
            float s = 0.f;
            #pragma unroll
            for(int o=0;o<DH;o++) s += sq[o*DH+d]*sk[o*DH+e];
            g_M[idx] = s;
        }
        return;
    }
    int b2 = b - 8192;
    int c = b2>>4, seg = b2&15;
    size_t base = ((size_t)c*TT + (size_t)seg*128)*EMB;
    #pragma unroll
    for(int j=0;j<4;j++){
        int e = tid + j*256;
        float acc = 0.f;
        const float* p = inp + base + e;
        #pragma unroll 4
        for(int t=0;t<128;t++) acc += p[(size_t)t*EMB];
        g_xpart[(size_t)b2*EMB + e] = acc;
    }
}

// ---------------- kernel 2: diag scores + vsum ----------------
__global__ __launch_bounds__(256) void k_diagv(const float* __restrict__ inp,
                                               const float* __restrict__ wv){
    if(blockIdx.x >= 16384){
        int b2 = blockIdx.x - 16384;
        int c = b2>>4, h = b2&15;
        __shared__ float xs[DH];
        int tid = threadIdx.x;
        if(tid < DH){
            float s = 0.f;
            #pragma unroll
            for(int seg=0;seg<16;seg++) s += g_xpart[(size_t)(c*16+seg)*EMB + h*DH + tid];
            xs[tid] = s;
        }
        __syncthreads();
        if(tid < DH){
            float s = 0.f;
            #pragma unroll
            for(int d=0;d<DH;d++) s += xs[d]*wv[tid*DH+d];
            g_vsum[c*EMB + h*DH + tid] = s;
        }
        return;
    }
    __shared__ float Ms[DH][DH];
    __shared__ float Xs[64][DH+1];
    __shared__ float ds[64];
    int g0 = blockIdx.x*64;
    int tid = threadIdx.x, tx = tid&15, ty = tid>>4;
    for(int i=tid;i<DH*DH;i+=256) (&Ms[0][0])[i] = g_M[i];
    {
        const float* src = inp + (size_t)g0*DH;
        for(int i=tid;i<64*(DH/4);i+=256){
            int r = i/(DH/4), q = i%(DH/4);
            float4 v = *(const float4*)(src + (size_t)r*DH + q*4);
            Xs[r][q*4+0]=v.x; Xs[r][q*4+1]=v.y; Xs[r][q*4+2]=v.z; Xs[r][q*4+3]=v.w;
        }
    }
    __syncthreads();
    float acc[4][4] = {};
    #pragma unroll 8
    for(int k=0;k<DH;k++){
        float a[4], b[4];
        #pragma unroll
        for(int i=0;i<4;i++) a[i] = Xs[ty*4+i][k];
        #pragma unroll
        for(int j=0;j<4;j++) b[j] = Ms[k][tx*4+j];
        #pragma unroll
        for(int i=0;i<4;i++)
            #pragma unroll
            for(int j=0;j<4;j++) acc[i][j] += a[i]*b[j];
    }
    #pragma unroll
    for(int i=0;i<4;i++){
        float p = 0.f;
        #pragma unroll
        for(int j=0;j<4;j++) p += acc[i][j]*Xs[ty*4+i][tx*4+j];
        #pragma unroll
        for(int off=8;off;off>>=1) p += __shfl_down_sync(0xffffffffu, p, off, 16);
        if(tx==0) ds[ty*4+i] = p;
    }
    __syncthreads();
    if(tid < 64) g_w[g0+tid] = ds[tid]*(1.0f/32.0f);
}

// ---------------- block reduction ----------------
__device__ __forceinline__ float blk_reduce(float v, float* red){
    int lane = threadIdx.x&31, w = threadIdx.x>>5;
    #pragma unroll
    for(int off=16;off;off>>=1) v += __shfl_down_sync(0xffffffffu, v, off);
    if(lane==0) red[w] = v;
    __syncthreads();
    if(w==0){
        float x = (lane<8)? red[lane] : 0.f;
        #pragma unroll
        for(int off=4;off;off>>=1) x += __shfl_down_sync(0xffffffffu, x, off);
        if(lane==0) red[0] = x;
    }
    __syncthreads();
    float r = red[0];
    __syncthreads();
    return r;
}

// ---------------- kernel 3: softmax + residual + LN1, fp16 out ----------------
__global__ __launch_bounds__(256) void k_ln1(const float* __restrict__ inp,
                                             const float* __restrict__ g1,
                                             const float* __restrict__ b1){
    __shared__ float red[8];
    __shared__ float ws[NH];
    int row = blockIdx.x, c = row>>11, t = row&2047;
    int tid = threadIdx.x;
    if(tid < NH){
        int h = tid;
        size_t idx = (size_t)t*NH + h;
        float d[CC], m = -1e30f;
        #pragma unroll
        for(int c2=0;c2<CC;c2++){
            d[c2] = g_w[(size_t)c2*(TT*NH) + idx];
            m = fmaxf(m, d[c2]);
        }
        float s = 0.f;
        #pragma unroll
        for(int c2=0;c2<CC;c2++) s += __expf(d[c2]-m);
        ws[h] = __expf(d[c]-m) / s;
    }
    __syncthreads();
    float x[4]; float s = 0.f;
    #pragma unroll
    for(int j=0;j<4;j++){
        int e = tid + j*256;
        float v = inp[(size_t)row*EMB + e] + ws[e>>6]*g_vsum[c*EMB + e];
        x[j] = v; s += v;
    }
    float mu = blk_reduce(s, red)*(1.f/EMB);
    float q = 0.f;
    #pragma unroll
    for(int j=0;j<4;j++){ float d = x[j]-mu; q += d*d; }
    float rstd = rsqrtf(blk_reduce(q, red)*(1.f/EMB) + EPS_LN);
    #pragma unroll
    for(int j=0;j<4;j++){
        int e = tid + j*256;
        float val = x[j] + (x[j]-mu)*rstd*g1[e] + b1[e];
        g_y1[(size_t)row*EMB + e] = __float2half_rn(val);
    }
}

// ---------------- final LN2 ----------------
__global__ __launch_bounds__(256) void k_ln2(float* __restrict__ out,
                                             const float* __restrict__ g2,
                                             const float* __restrict__ b2){
    __shared__ float red[8];
    int row = blockIdx.x;
    int tid = threadIdx.x;
    float x[4]; float s = 0.f;
    #pragma unroll
    for(int j=0;j<4;j++){
        int e = tid + j*256;
        x[j] = out[(size_t)row*EMB + e]; s += x[j];
    }
    float mu = blk_reduce(s, red)*(1.f/EMB);
    float q = 0.f;
    #pragma unroll
    for(int j=0;j<4;j++){ float d = x[j]-mu; q += d*d; }
    float rstd = rsqrtf(blk_reduce(q, red)*(1.f/EMB) + EPS_LN);
    #pragma unroll
    for(int j=0;j<4;j++){
        int e = tid + j*256;
        out[(size_t)row*EMB + e] = (x[j]-mu)*rstd*g2[e] + b2[e];
    }
}

// ---------------- plain fp16 warp-MMA GEMM ----------------
// C[M,N] = A[M,K] @ B[N,K]^T + bias.  A, B plain fp16 row-major.
// CTA 128x128, 256 thr (8 warps 4Mx2N, warp 32x64), BK=32, 3-stage, 2 CTAs/SM.
#define T_STRIDE 80                       // 64B data + 16B pad
#define T_BYTES (128*T_STRIDE)            // 10240
#define STAGE_BYTES (2*T_BYTES)           // 20480
#define GEMM_SMEM (3*STAGE_BYTES)         // 61440

template<int HALF_OUT>
__global__ __launch_bounds__(256, 2) void k_gemm_mma(
    const __half* __restrict__ A,
    const __half* __restrict__ B,
    const float* __restrict__ bias,
    float* __restrict__ Cf,
    __half* __restrict__ Cs,
    int Ka, int Nfull)
{
    extern __shared__ char smem_raw[];
    const uint32_t sb = smem_u32(smem_raw);
    const int tid = threadIdx.x;
    const int wid = tid >> 5, lane = tid & 31;
    const int wm = wid & 3, wn = wid >> 2;   // 4 x 2 warp grid, warp tile 32x64

    const size_t bm = (size_t)blockIdx.y * 128;
    const size_t bn = (size_t)blockIdx.x * 128;
    const int NKC = Ka >> 5;                 // 32 real k per chunk

    const char* Ag = (const char*)(A + bm * (size_t)Ka);
    const char* Bg = (const char*)(B + bn * (size_t)Ka);
    const size_t rstride = (size_t)Ka * 2;

    const int ldr = tid >> 2;                // 0..63
    const int ldc = (tid & 3) << 4;          // 16B segment in 64B row

    auto load_stage = [&](int kc){
        uint32_t st = sb + (kc%3)*STAGE_BYTES;
        size_t gofs = (size_t)kc*64;
        #pragma unroll
        for(int i=0;i<2;i++){
            int r = ldr + i*64;
            cp16(st + r*T_STRIDE + ldc, Ag + (size_t)r*rstride + gofs + ldc);
        }
        #pragma unroll
        for(int i=0;i<2;i++){
            int r = ldr + i*64;
            cp16(st + T_BYTES + r*T_STRIDE + ldc, Bg + (size_t)r*rstride + gofs + ldc);
        }
        cp_commit();
    };

    float acc[2][8][4];
    #pragma unroll
    for(int i=0;i<2;i++)
        #pragma unroll
        for(int j=0;j<8;j++)
            #pragma unroll
            for(int q=0;q<4;q++) acc[i][j][q] = 0.f;

    load_stage(0); load_stage(1);

    const uint32_t lrow = lane & 15;
    const uint32_t lcol = (lane >> 4) << 4;

    for(int kc=0; kc<NKC; kc++){
        cp_wait1();
        __syncthreads();
        if (kc+2 < NKC) load_stage(kc+2);

        uint32_t sA = sb + (kc%3)*STAGE_BYTES;
        uint32_t sB = sA + T_BYTES;
        uint32_t aBase = sA + (wm*32 + lrow)*T_STRIDE + lcol;
        uint32_t bBase = sB + (wn*64 + lrow)*T_STRIDE + lcol;

        #pragma unroll
        for(int s=0;s<2;s++){          // two k16 steps per chunk
            uint32_t af[2][4];         // [mtile]
            uint32_t bf[4][4];         // [ntile16]
            #pragma unroll
            for(int i=0;i<2;i++)
                ldm4(aBase + i*16*T_STRIDE + s*32, af[i]);
            #pragma unroll
            for(int j=0;j<4;j++)
                ldm4(bBase + j*16*T_STRIDE + s*32, bf[j]);

            #pragma unroll
            for(int i=0;i<2;i++){
                #pragma unroll
                for(int j=0;j<4;j++){
                    mma16816(acc[i][2*j],   af[i], bf[j][0], bf[j][2]);
                    mma16816(acc[i][2*j+1], af[i], bf[j][1], bf[j][3]);
                }
            }
        }
    }
    cp_wait0();

    // epilogue
    const int r4 = lane >> 2, c2 = (lane & 3) << 1;
    #pragma unroll
    for(int i=0;i<2;i++){
        size_t row0 = bm + wm*32 + i*16 + r4;
        #pragma unroll
        for(int j=0;j<8;j++){
            size_t n0 = bn + wn*64 + j*8 + c2;
            float b0 = bias[n0], b1 = bias[n0+1];
            float v00 = acc[i][j][0] + b0, v01 = acc[i][j][1] + b1;
            float v10 = acc[i][j][2] + b0, v11 = acc[i][j][3] + b1;
            if (HALF_OUT){
                *(uint32_t*)(Cs + row0*(size_t)Nfull + n0) =
                    packh(__float2half_rn(v00), __float2half_rn(v01));
                *(uint32_t*)(Cs + (row0+8)*(size_t)Nfull + n0) =
                    packh(__float2half_rn(v10), __float2half_rn(v11));
            } else {
                float* d0 = Cf + row0*(size_t)Nfull + n0;
                float* d1 = Cf + (row0+8)*(size_t)Nfull + n0;
                d0[0] = v00; d0[1] = v01;
                d1[0] = v10; d1[1] = v11;
            }
        }
    }
}

// ---------------- launch ----------------
extern "C" void kernel_launch(void* const* d_in, const int* in_sizes, int n_in,
                              void* d_out, int out_size){
    const float* inp   = (const float*)d_in[0];
    const float* wq    = (const float*)d_in[1];
    const float* wk    = (const float*)d_in[2];
    const float* wv    = (const float*)d_in[3];
    const float* ln1_g = (const float*)d_in[4];
    const float* ln1_b = (const float*)d_in[5];
    const float* fc1_w = (const float*)d_in[6];
    const float* fc1_b = (const float*)d_in[7];
    const float* fc2_w = (const float*)d_in[8];
    const float* fc2_b = (const float*)d_in[9];
    const float* ln2_g = (const float*)d_in[10];
    const float* ln2_b = (const float*)d_in[11];
    float* out = (float*)d_out;

    __half *y1p=nullptr, *h1p=nullptr, *w1p=nullptr, *w2p=nullptr;
    cudaGetSymbolAddress((void**)&y1p, g_y1);
    cudaGetSymbolAddress((void**)&h1p, g_h1);
    cudaGetSymbolAddress((void**)&w1p, g_w1);
    cudaGetSymbolAddress((void**)&w2p, g_w2);

    cudaFuncSetAttribute(k_gemm_mma<1>, cudaFuncAttributeMaxDynamicSharedMemorySize, GEMM_SMEM);
    cudaFuncSetAttribute(k_gemm_mma<0>, cudaFuncAttributeMaxDynamicSharedMemorySize, GEMM_SMEM);

    // launch 1: weight fp16 cast + xsum partials + prep_M
    k_presplit<<<8705, 256>>>(inp, wq, wk, fc1_w, fc2_w, w1p, w2p);
    // launch 2
    k_diagv<<<16384+512, 256>>>(inp, wv);
    // launch 3
    k_ln1<<<NROWS, 256>>>(inp, ln1_g, ln1_b);

    // launch 4: h = y @ fc1_w^T + b1 (fp16 out) — ncu slot
    k_gemm_mma<1><<<dim3(MAPD/128, NROWS/128), 256, GEMM_SMEM>>>(
        y1p, w1p, fc1_b, nullptr, h1p, EMB, MAPD);
    // launch 5: out = h @ fc2_w^T + b2 (fp32 out)
    k_gemm_mma<0><<<dim3(EMB/128, NROWS/128), 256, GEMM_SMEM>>>(
        h1p, w2p, fc2_b, out, nullptr, MAPD, EMB);

    k_ln2<<<NROWS, 256>>>(out, ln2_g, ln2_b);
}

// round 11
// speedup vs baseline: 2.4136x; 1.0102x over previous
#include <cuda_runtime.h>
#include <cuda_bf16.h>
#include <cuda_fp16.h>
#include <cstdint>

#define CC 32
#define TT 2048
#define EMB 1024
#define NH 16
#define DH 64
#define MAPD 4096
#define NROWS (CC*TT)          // 65536
#define EPS_LN 1e-5f

// ---------------- scratch (static device globals) ----------------
__device__ float g_M[DH*DH];
__device__ float g_xpart[512*EMB];
__device__ float g_vsum[CC*EMB];
__device__ float g_w[NROWS*NH];
// everything plain fp16 row-major
__device__ __align__(128) __half g_y1[(size_t)NROWS*EMB];      // 134 MB
__device__ __align__(128) __half g_h1[(size_t)NROWS*MAPD];     // 536 MB
__device__ __align__(128) __half g_w1[(size_t)MAPD*EMB];       // 8 MB
__device__ __align__(128) __half g_w2[(size_t)EMB*MAPD];       // 8 MB

// ---------------- helpers ----------------
__device__ __forceinline__ uint32_t smem_u32(const void* p){
    uint32_t a;
    asm("{ .reg .u64 t; cvta.to.shared.u64 t, %1; cvt.u32.u64 %0, t; }" : "=r"(a) : "l"(p));
    return a;
}
__device__ __forceinline__ void cp16(uint32_t dst, const void* src){
    asm volatile("cp.async.cg.shared.global [%0], [%1], 16;" :: "r"(dst), "l"(src) : "memory");
}
__device__ __forceinline__ void cp_commit(){ asm volatile("cp.async.commit_group;" ::: "memory"); }
__device__ __forceinline__ void cp_wait2(){ asm volatile("cp.async.wait_group 2;" ::: "memory"); }
__device__ __forceinline__ void cp_wait0(){ asm volatile("cp.async.wait_group 0;" ::: "memory"); }

__device__ __forceinline__ void ldm4(uint32_t a, uint32_t* r){
    asm volatile("ldmatrix.sync.aligned.m8n8.x4.shared.b16 {%0,%1,%2,%3}, [%4];"
        : "=r"(r[0]), "=r"(r[1]), "=r"(r[2]), "=r"(r[3]) : "r"(a));
}
__device__ __forceinline__ void mma16816(float* d, const uint32_t* a, uint32_t b0, uint32_t b1){
    asm volatile("mma.sync.aligned.m16n8k16.row.col.f32.f16.f16.f32 "
        "{%0,%1,%2,%3}, {%4,%5,%6,%7}, {%8,%9}, {%0,%1,%2,%3};"
        : "+f"(d[0]), "+f"(d[1]), "+f"(d[2]), "+f"(d[3])
        : "r"(a[0]), "r"(a[1]), "r"(a[2]), "r"(a[3]), "r"(b0), "r"(b1));
}
__device__ __forceinline__ uint32_t packh(__half a, __half b){
    return (uint32_t)(*(unsigned short*)&a) | ((uint32_t)(*(unsigned short*)&b) << 16);
}

// ---------------- kernel 1: weight fp16 cast + partial xsum + prep_M ----------------
__global__ void k_presplit(const float* __restrict__ inp,
                           const float* __restrict__ wq, const float* __restrict__ wk,
                           const float* __restrict__ w1src, const float* __restrict__ w2src,
                           __half* __restrict__ d1, __half* __restrict__ d2){
    int b = blockIdx.x, tid = threadIdx.x;
    if(b < 8192){
        const float* src; __half* dst; int i;
        if(b < 4096){ src = w1src; dst = d1; i = b*256 + tid; }
        else        { src = w2src; dst = d2; i = (b-4096)*256 + tid; }
        int base = i*4;
        float4 v = *(const float4*)(src + base);
        *(uint2*)(dst + base) = make_uint2(
            packh(__float2half_rn(v.x), __float2half_rn(v.y)),
            packh(__float2half_rn(v.z), __float2half_rn(v.w)));
        return;
    }
    if(b == 8704){
        __shared__ float sq[DH*DH], sk[DH*DH];
        for(int i=tid;i<DH*DH;i+=256){ sq[i]=wq[i]; sk[i]=wk[i]; }
        __syncthreads();
        for(int idx=tid; idx<DH*DH; idx+=256){
            int d = idx/DH, e = idx%DH;
            float s = 0.f;
            #pragma unroll
            for(int o=0;o<DH;o++) s += sq[o*DH+d]*sk[o*DH+e];
            g_M[idx] = s;
        }
        return;
    }
    int b2 = b - 8192;
    int c = b2>>4, seg = b2&15;
    size_t base = ((size_t)c*TT + (size_t)seg*128)*EMB;
    #pragma unroll
    for(int j=0;j<4;j++){
        int e = tid + j*256;
        float acc = 0.f;
        const float* p = inp + base + e;
        #pragma unroll 4
        for(int t=0;t<128;t++) acc += p[(size_t)t*EMB];
        g_xpart[(size_t)b2*EMB + e] = acc;
    }
}

// ---------------- kernel 2: diag scores + vsum ----------------
__global__ __launch_bounds__(256) void k_diagv(const float* __restrict__ inp,
                                               const float* __restrict__ wv){
    if(blockIdx.x >= 16384){
        int b2 = blockIdx.x - 16384;
        int c = b2>>4, h = b2&15;
        __shared__ float xs[DH];
        int tid = threadIdx.x;
        if(tid < DH){
            float s = 0.f;
            #pragma unroll
            for(int seg=0;seg<16;seg++) s += g_xpart[(size_t)(c*16+seg)*EMB + h*DH + tid];
            xs[tid] = s;
        }
        __syncthreads();
        if(tid < DH){
            float s = 0.f;
            #pragma unroll
            for(int d=0;d<DH;d++) s += xs[d]*wv[tid*DH+d];
            g_vsum[c*EMB + h*DH + tid] = s;
        }
        return;
    }
    __shared__ float Ms[DH][DH];
    __shared__ float Xs[64][DH+1];
    __shared__ float ds[64];
    int g0 = blockIdx.x*64;
    int tid = threadIdx.x, tx = tid&15, ty = tid>>4;
    for(int i=tid;i<DH*DH;i+=256) (&Ms[0][0])[i] = g_M[i];
    {
        const float* src = inp + (size_t)g0*DH;
        for(int i=tid;i<64*(DH/4);i+=256){
            int r = i/(DH/4), q = i%(DH/4);
            float4 v = *(const float4*)(src + (size_t)r*DH + q*4);
            Xs[r][q*4+0]=v.x; Xs[r][q*4+1]=v.y; Xs[r][q*4+2]=v.z; Xs[r][q*4+3]=v.w;
        }
    }
    __syncthreads();
    float acc[4][4] = {};
    #pragma unroll 8
    for(int k=0;k<DH;k++){
        float a[4], b[4];
        #pragma unroll
        for(int i=0;i<4;i++) a[i] = Xs[ty*4+i][k];
        #pragma unroll
        for(int j=0;j<4;j++) b[j] = Ms[k][tx*4+j];
        #pragma unroll
        for(int i=0;i<4;i++)
            #pragma unroll
            for(int j=0;j<4;j++) acc[i][j] += a[i]*b[j];
    }
    #pragma unroll
    for(int i=0;i<4;i++){
        float p = 0.f;
        #pragma unroll
        for(int j=0;j<4;j++) p += acc[i][j]*Xs[ty*4+i][tx*4+j];
        #pragma unroll
        for(int off=8;off;off>>=1) p += __shfl_down_sync(0xffffffffu, p, off, 16);
        if(tx==0) ds[ty*4+i] = p;
    }
    __syncthreads();
    if(tid < 64) g_w[g0+tid] = ds[tid]*(1.0f/32.0f);
}

// ---------------- block reduction ----------------
__device__ __forceinline__ float blk_reduce(float v, float* red){
    int lane = threadIdx.x&31, w = threadIdx.x>>5;
    #pragma unroll
    for(int off=16;off;off>>=1) v += __shfl_down_sync(0xffffffffu, v, off);
    if(lane==0) red[w] = v;
    __syncthreads();
    if(w==0){
        float x = (lane<8)? red[lane] : 0.f;
        #pragma unroll
        for(int off=4;off;off>>=1) x += __shfl_down_sync(0xffffffffu, x, off);
        if(lane==0) red[0] = x;
    }
    __syncthreads();
    float r = red[0];
    __syncthreads();
    return r;
}

// ---------------- kernel 3: softmax + residual + LN1, fp16 out ----------------
__global__ __launch_bounds__(256) void k_ln1(const float* __restrict__ inp,
                                             const float* __restrict__ g1,
                                             const float* __restrict__ b1){
    __shared__ float red[8];
    __shared__ float sw[CC*NH];   // all 32 c-values for the 16 heads of this t
    __shared__ float ws[NH];
    int row = blockIdx.x, c = row>>11, t = row&2047;
    int tid = threadIdx.x;
    // cooperative coalesced load of g_w[:, t, :] (32 segments of 64B)
    #pragma unroll
    for(int i=0;i<2;i++){
        int idx = tid + i*256;   // 0..511 = c*16 + h
        int cc = idx >> 4, h = idx & 15;
        sw[idx] = g_w[(size_t)cc*(TT*NH) + (size_t)t*NH + h];
    }
    __syncthreads();
    if(tid < NH){
        int h = tid;
        float m = -1e30f;
        #pragma unroll
        for(int c2=0;c2<CC;c2++) m = fmaxf(m, sw[c2*NH + h]);
        float s = 0.f;
        #pragma unroll
        for(int c2=0;c2<CC;c2++) s += __expf(sw[c2*NH + h]-m);
        ws[h] = __expf(sw[c*NH + h]-m) / s;
    }
    __syncthreads();
    float x[4]; float s = 0.f;
    #pragma unroll
    for(int j=0;j<4;j++){
        int e = tid + j*256;
        float v = inp[(size_t)row*EMB + e] + ws[e>>6]*g_vsum[c*EMB + e];
        x[j] = v; s += v;
    }
    float mu = blk_reduce(s, red)*(1.f/EMB);
    float q = 0.f;
    #pragma unroll
    for(int j=0;j<4;j++){ float d = x[j]-mu; q += d*d; }
    float rstd = rsqrtf(blk_reduce(q, red)*(1.f/EMB) + EPS_LN);
    #pragma unroll
    for(int j=0;j<4;j++){
        int e = tid + j*256;
        float val = x[j] + (x[j]-mu)*rstd*g1[e] + b1[e];
        g_y1[(size_t)row*EMB + e] = __float2half_rn(val);
    }
}

// ---------------- final LN2 ----------------
__global__ __launch_bounds__(256) void k_ln2(float* __restrict__ out,
                                             const float* __restrict__ g2,
                                             const float* __restrict__ b2){
    __shared__ float red[8];
    int row = blockIdx.x;
    int tid = threadIdx.x;
    float x[4]; float s = 0.f;
    #pragma unroll
    for(int j=0;j<4;j++){
        int e = tid + j*256;
        x[j] = out[(size_t)row*EMB + e]; s += x[j];
    }
    float mu = blk_reduce(s, red)*(1.f/EMB);
    float q = 0.f;
    #pragma unroll
    for(int j=0;j<4;j++){ float d = x[j]-mu; q += d*d; }
    float rstd = rsqrtf(blk_reduce(q, red)*(1.f/EMB) + EPS_LN);
    #pragma unroll
    for(int j=0;j<4;j++){
        int e = tid + j*256;
        out[(size_t)row*EMB + e] = (x[j]-mu)*rstd*g2[e] + b2[e];
    }
}

// ---------------- plain fp16 warp-MMA GEMM ----------------
// C[M,N] = A[M,K] @ B[N,K]^T + bias.  A, B plain fp16 row-major.
// CTA 128x128, 256 thr (8 warps 4Mx2N, warp 32x64), BK=32,
// 4-stage cp.async (wait_group 2), 2 CTAs/SM.
#define T_STRIDE 80                       // 64B data + 16B pad
#define T_BYTES (128*T_STRIDE)            // 10240
#define STAGE_BYTES (2*T_BYTES)           // 20480
#define NSTAGE 4
#define GEMM_SMEM (NSTAGE*STAGE_BYTES)    // 81920 -> 2 CTAs/SM

template<int HALF_OUT>
__global__ __launch_bounds__(256, 2) void k_gemm_mma(
    const __half* __restrict__ A,
    const __half* __restrict__ B,
    const float* __restrict__ bias,
    float* __restrict__ Cf,
    __half* __restrict__ Cs,
    int Ka, int Nfull)
{
    extern __shared__ char smem_raw[];
    const uint32_t sb = smem_u32(smem_raw);
    const int tid = threadIdx.x;
    const int wid = tid >> 5, lane = tid & 31;
    const int wm = wid & 3, wn = wid >> 2;   // 4 x 2 warp grid, warp tile 32x64

    const size_t bm = (size_t)blockIdx.y * 128;
    const size_t bn = (size_t)blockIdx.x * 128;
    const int NKC = Ka >> 5;                 // 32 real k per chunk

    const char* Ag = (const char*)(A + bm * (size_t)Ka);
    const char* Bg = (const char*)(B + bn * (size_t)Ka);
    const size_t rstride = (size_t)Ka * 2;

    const int ldr = tid >> 2;                // 0..63
    const int ldc = (tid & 3) << 4;          // 16B segment in 64B row

    auto load_stage = [&](int kc){
        uint32_t st = sb + (kc & 3)*STAGE_BYTES;
        size_t gofs = (size_t)kc*64;
        #pragma unroll
        for(int i=0;i<2;i++){
            int r = ldr + i*64;
            cp16(st + r*T_STRIDE + ldc, Ag + (size_t)r*rstride + gofs + ldc);
        }
        #pragma unroll
        for(int i=0;i<2;i++){
            int r = ldr + i*64;
            cp16(st + T_BYTES + r*T_STRIDE + ldc, Bg + (size_t)r*rstride + gofs + ldc);
        }
        cp_commit();
    };

    float acc[2][8][4];
    #pragma unroll
    for(int i=0;i<2;i++)
        #pragma unroll
        for(int j=0;j<8;j++)
            #pragma unroll
            for(int q=0;q<4;q++) acc[i][j][q] = 0.f;

    load_stage(0); load_stage(1); load_stage(2);

    const uint32_t lrow = lane & 15;
    const uint32_t lcol = (lane >> 4) << 4;

    for(int kc=0; kc<NKC; kc++){
        cp_wait2();
        __syncthreads();
        if (kc+3 < NKC) load_stage(kc+3);

        uint32_t sA = sb + (kc & 3)*STAGE_BYTES;
        uint32_t sB = sA + T_BYTES;
        uint32_t aBase = sA + (wm*32 + lrow)*T_STRIDE + lcol;
        uint32_t bBase = sB + (wn*64 + lrow)*T_STRIDE + lcol;

        #pragma unroll
        for(int s=0;s<2;s++){          // two k16 steps per chunk
            uint32_t af[2][4];         // [mtile]
            uint32_t bf[4][4];         // [ntile16]
            #pragma unroll
            for(int i=0;i<2;i++)
                ldm4(aBase + i*16*T_STRIDE + s*32, af[i]);
            #pragma unroll
            for(int j=0;j<4;j++)
                ldm4(bBase + j*16*T_STRIDE + s*32, bf[j]);

            #pragma unroll
            for(int i=0;i<2;i++){
                #pragma unroll
                for(int j=0;j<4;j++){
                    mma16816(acc[i][2*j],   af[i], bf[j][0], bf[j][2]);
                    mma16816(acc[i][2*j+1], af[i], bf[j][1], bf[j][3]);
                }
            }
        }
    }
    cp_wait0();

    // epilogue
    const int r4 = lane >> 2, c2 = (lane & 3) << 1;
    #pragma unroll
    for(int i=0;i<2;i++){
        size_t row0 = bm + wm*32 + i*16 + r4;
        #pragma unroll
        for(int j=0;j<8;j++){
            size_t n0 = bn + wn*64 + j*8 + c2;
            float b0 = bias[n0], b1 = bias[n0+1];
            float v00 = acc[i][j][0] + b0, v01 = acc[i][j][1] + b1;
            float v10 = acc[i][j][2] + b0, v11 = acc[i][j][3] + b1;
            if (HALF_OUT){
                *(uint32_t*)(Cs + row0*(size_t)Nfull + n0) =
                    packh(__float2half_rn(v00), __float2half_rn(v01));
                *(uint32_t*)(Cs + (row0+8)*(size_t)Nfull + n0) =
                    packh(__float2half_rn(v10), __float2half_rn(v11));
            } else {
                float* d0 = Cf + row0*(size_t)Nfull + n0;
                float* d1 = Cf + (row0+8)*(size_t)Nfull + n0;
                d0[0] = v00; d0[1] = v01;
                d1[0] = v10; d1[1] = v11;
            }
        }
    }
}

// ---------------- launch ----------------
extern "C" void kernel_launch(void* const* d_in, const int* in_sizes, int n_in,
                              void* d_out, int out_size){
    const float* inp   = (const float*)d_in[0];
    const float* wq    = (const float*)d_in[1];
    const float* wk    = (const float*)d_in[2];
    const float* wv    = (const float*)d_in[3];
    const float* ln1_g = (const float*)d_in[4];
    const float* ln1_b = (const float*)d_in[5];
    const float* fc1_w = (const float*)d_in[6];
    const float* fc1_b = (const float*)d_in[7];
    const float* fc2_w = (const float*)d_in[8];
    const float* fc2_b = (const float*)d_in[9];
    const float* ln2_g = (const float*)d_in[10];
    const float* ln2_b = (const float*)d_in[11];
    float* out = (float*)d_out;

    __half *y1p=nullptr, *h1p=nullptr, *w1p=nullptr, *w2p=nullptr;
    cudaGetSymbolAddress((void**)&y1p, g_y1);
    cudaGetSymbolAddress((void**)&h1p, g_h1);
    cudaGetSymbolAddress((void**)&w1p, g_w1);
    cudaGetSymbolAddress((void**)&w2p, g_w2);

    cudaFuncSetAttribute(k_gemm_mma<1>, cudaFuncAttributeMaxDynamicSharedMemorySize, GEMM_SMEM);
    cudaFuncSetAttribute(k_gemm_mma<0>, cudaFuncAttributeMaxDynamicSharedMemorySize, GEMM_SMEM);

    // launch 1: weight fp16 cast + xsum partials + prep_M
    k_presplit<<<8705, 256>>>(inp, wq, wk, fc1_w, fc2_w, w1p, w2p);
    // launch 2
    k_diagv<<<16384+512, 256>>>(inp, wv);
    // launch 3
    k_ln1<<<NROWS, 256>>>(inp, ln1_g, ln1_b);

    // launch 4: h = y @ fc1_w^T + b1 (fp16 out) — ncu slot
    k_gemm_mma<1><<<dim3(MAPD/128, NROWS/128), 256, GEMM_SMEM>>>(
        y1p, w1p, fc1_b, nullptr, h1p, EMB, MAPD);
    // launch 5: out = h @ fc2_w^T + b2 (fp32 out)
    k_gemm_mma<0><<<dim3(EMB/128, NROWS/128), 256, GEMM_SMEM>>>(
        h1p, w2p, fc2_b, out, nullptr, MAPD, EMB);

    k_ln2<<<NROWS, 256>>>(out, ln2_g, ln2_b);
}

// round 12
// speedup vs baseline: 2.8198x; 1.1683x over previous
#include <cuda_runtime.h>
#include <cuda_bf16.h>
#include <cuda_fp16.h>
#include <cstdint>

#define CC 32
#define TT 2048
#define EMB 1024
#define NH 16
#define DH 64
#define MAPD 4096
#define NROWS (CC*TT)          // 65536
#define EPS_LN 1e-5f

// ---------------- scratch (static device globals) ----------------
__device__ float g_M[DH*DH];
__device__ float g_xpart[512*EMB];
__device__ float g_vsum[CC*EMB];
__device__ float g_w[NROWS*NH];
// everything plain fp16 row-major
__device__ __align__(128) __half g_y1[(size_t)NROWS*EMB];      // 134 MB
__device__ __align__(128) __half g_h1[(size_t)NROWS*MAPD];     // 536 MB
__device__ __align__(128) __half g_w1[(size_t)MAPD*EMB];       // 8 MB
__device__ __align__(128) __half g_w2[(size_t)EMB*MAPD];       // 8 MB

// ---------------- helpers ----------------
__device__ __forceinline__ uint32_t smem_u32(const void* p){
    uint32_t a;
    asm("{ .reg .u64 t; cvta.to.shared.u64 t, %1; cvt.u32.u64 %0, t; }" : "=r"(a) : "l"(p));
    return a;
}
__device__ __forceinline__ void cp16(uint32_t dst, const void* src){
    asm volatile("cp.async.cg.shared.global [%0], [%1], 16;" :: "r"(dst), "l"(src) : "memory");
}
__device__ __forceinline__ void cp_commit(){ asm volatile("cp.async.commit_group;" ::: "memory"); }
__device__ __forceinline__ void cp_wait1(){ asm volatile("cp.async.wait_group 1;" ::: "memory"); }
__device__ __forceinline__ void cp_wait0(){ asm volatile("cp.async.wait_group 0;" ::: "memory"); }

__device__ __forceinline__ void ldm4(uint32_t a, uint32_t* r){
    asm volatile("ldmatrix.sync.aligned.m8n8.x4.shared.b16 {%0,%1,%2,%3}, [%4];"
        : "=r"(r[0]), "=r"(r[1]), "=r"(r[2]), "=r"(r[3]) : "r"(a));
}
__device__ __forceinline__ void mma16816(float* d, const uint32_t* a, uint32_t b0, uint32_t b1){
    asm volatile("mma.sync.aligned.m16n8k16.row.col.f32.f16.f16.f32 "
        "{%0,%1,%2,%3}, {%4,%5,%6,%7}, {%8,%9}, {%0,%1,%2,%3};"
        : "+f"(d[0]), "+f"(d[1]), "+f"(d[2]), "+f"(d[3])
        : "r"(a[0]), "r"(a[1]), "r"(a[2]), "r"(a[3]), "r"(b0), "r"(b1));
}
__device__ __forceinline__ uint32_t packh(__half a, __half b){
    return (uint32_t)(*(unsigned short*)&a) | ((uint32_t)(*(unsigned short*)&b) << 16);
}
__device__ __forceinline__ uint32_t sw128(uint32_t off){
    return off ^ ((off >> 3) & 0x70);
}

// ---------------- kernel 1: weight fp16 cast + partial xsum + prep_M ----------------
__global__ void k_presplit(const float* __restrict__ inp,
                           const float* __restrict__ wq, const float* __restrict__ wk,
                           const float* __restrict__ w1src, const float* __restrict__ w2src,
                           __half* __restrict__ d1, __half* __restrict__ d2){
    int b = blockIdx.x, tid = threadIdx.x;
    if(b < 8192){
        const float* src; __half* dst; int i;
        if(b < 4096){ src = w1src; dst = d1; i = b*256 + tid; }
        else        { src = w2src; dst = d2; i = (b-4096)*256 + tid; }
        int base = i*4;
        float4 v = *(const float4*)(src + base);
        *(uint2*)(dst + base) = make_uint2(
            packh(__float2half_rn(v.x), __float2half_rn(v.y)),
            packh(__float2half_rn(v.z), __float2half_rn(v.w)));
        return;
    }
    if(b == 8704){
        __shared__ float sq[DH*DH], sk[DH*DH];
        for(int i=tid;i<DH*DH;i+=256){ sq[i]=wq[i]; sk[i]=wk[i]; }
        __syncthreads();
        for(int idx=tid; idx<DH*DH; idx+=256){
            int d = idx/DH, e = idx%DH;
            float s = 0.f;
            #pragma unroll
            for(int o=0;o<DH;o++) s += sq[o*DH+d]*sk[o*DH+e];
            g_M[idx] = s;
        }
        return;
    }
    int b2 = b - 8192;
    int c = b2>>4, seg = b2&15;
    size_t base = ((size_t)c*TT + (size_t)seg*128)*EMB;
    #pragma unroll
    for(int j=0;j<4;j++){
        int e = tid + j*256;
        float acc = 0.f;
        const float* p = inp + base + e;
        #pragma unroll 4
        for(int t=0;t<128;t++) acc += p[(size_t)t*EMB];
        g_xpart[(size_t)b2*EMB + e] = acc;
    }
}

// ---------------- kernel 2: diag scores + vsum ----------------
__global__ __launch_bounds__(256) void k_diagv(const float* __restrict__ inp,
                                               const float* __restrict__ wv){
    if(blockIdx.x >= 16384){
        int b2 = blockIdx.x - 16384;
        int c = b2>>4, h = b2&15;
        __shared__ float xs[DH];
        int tid = threadIdx.x;
        if(tid < DH){
            float s = 0.f;
            #pragma unroll
            for(int seg=0;seg<16;seg++) s += g_xpart[(size_t)(c*16+seg)*EMB + h*DH + tid];
            xs[tid] = s;
        }
        __syncthreads();
        if(tid < DH){
            float s = 0.f;
            #pragma unroll
            for(int d=0;d<DH;d++) s += xs[d]*wv[tid*DH+d];
            g_vsum[c*EMB + h*DH + tid] = s;
        }
        return;
    }
    __shared__ float Ms[DH][DH];
    __shared__ float Xs[64][DH+1];
    __shared__ float ds[64];
    int g0 = blockIdx.x*64;
    int tid = threadIdx.x, tx = tid&15, ty = tid>>4;
    for(int i=tid;i<DH*DH;i+=256) (&Ms[0][0])[i] = g_M[i];
    {
        const float* src = inp + (size_t)g0*DH;
        for(int i=tid;i<64*(DH/4);i+=256){
            int r = i/(DH/4), q = i%(DH/4);
            float4 v = *(const float4*)(src + (size_t)r*DH + q*4);
            Xs[r][q*4+0]=v.x; Xs[r][q*4+1]=v.y; Xs[r][q*4+2]=v.z; Xs[r][q*4+3]=v.w;
        }
    }
    __syncthreads();
    float acc[4][4] = {};
    #pragma unroll 8
    for(int k=0;k<DH;k++){
        float a[4], b[4];
        #pragma unroll
        for(int i=0;i<4;i++) a[i] = Xs[ty*4+i][k];
        #pragma unroll
        for(int j=0;j<4;j++) b[j] = Ms[k][tx*4+j];
        #pragma unroll
        for(int i=0;i<4;i++)
            #pragma unroll
            for(int j=0;j<4;j++) acc[i][j] += a[i]*b[j];
    }
    #pragma unroll
    for(int i=0;i<4;i++){
        float p = 0.f;
        #pragma unroll
        for(int j=0;j<4;j++) p += acc[i][j]*Xs[ty*4+i][tx*4+j];
        #pragma unroll
        for(int off=8;off;off>>=1) p += __shfl_down_sync(0xffffffffu, p, off, 16);
        if(tx==0) ds[ty*4+i] = p;
    }
    __syncthreads();
    if(tid < 64) g_w[g0+tid] = ds[tid]*(1.0f/32.0f);
}

// ---------------- block reduction ----------------
__device__ __forceinline__ float blk_reduce(float v, float* red){
    int lane = threadIdx.x&31, w = threadIdx.x>>5;
    #pragma unroll
    for(int off=16;off;off>>=1) v += __shfl_down_sync(0xffffffffu, v, off);
    if(lane==0) red[w] = v;
    __syncthreads();
    if(w==0){
        float x = (lane<8)? red[lane] : 0.f;
        #pragma unroll
        for(int off=4;off;off>>=1) x += __shfl_down_sync(0xffffffffu, x, off);
        if(lane==0) red[0] = x;
    }
    __syncthreads();
    float r = red[0];
    __syncthreads();
    return r;
}

// ---------------- kernel 3: softmax + residual + LN1, fp16 out ----------------
__global__ __launch_bounds__(256) void k_ln1(const float* __restrict__ inp,
                                             const float* __restrict__ g1,
                                             const float* __restrict__ b1){
    __shared__ float red[8];
    __shared__ float sw[CC*NH];
    __shared__ float ws[NH];
    int row = blockIdx.x, c = row>>11, t = row&2047;
    int tid = threadIdx.x;
    #pragma unroll
    for(int i=0;i<2;i++){
        int idx = tid + i*256;
        int cc = idx >> 4, h = idx & 15;
        sw[idx] = g_w[(size_t)cc*(TT*NH) + (size_t)t*NH + h];
    }
    __syncthreads();
    if(tid < NH){
        int h = tid;
        float m = -1e30f;
        #pragma unroll
        for(int c2=0;c2<CC;c2++) m = fmaxf(m, sw[c2*NH + h]);
        float s = 0.f;
        #pragma unroll
        for(int c2=0;c2<CC;c2++) s += __expf(sw[c2*NH + h]-m);
        ws[h] = __expf(sw[c*NH + h]-m) / s;
    }
    __syncthreads();
    float x[4]; float s = 0.f;
    #pragma unroll
    for(int j=0;j<4;j++){
        int e = tid + j*256;
        float v = inp[(size_t)row*EMB + e] + ws[e>>6]*g_vsum[c*EMB + e];
        x[j] = v; s += v;
    }
    float mu = blk_reduce(s, red)*(1.f/EMB);
    float q = 0.f;
    #pragma unroll
    for(int j=0;j<4;j++){ float d = x[j]-mu; q += d*d; }
    float rstd = rsqrtf(blk_reduce(q, red)*(1.f/EMB) + EPS_LN);
    #pragma unroll
    for(int j=0;j<4;j++){
        int e = tid + j*256;
        float val = x[j] + (x[j]-mu)*rstd*g1[e] + b1[e];
        g_y1[(size_t)row*EMB + e] = __float2half_rn(val);
    }
}

// ---------------- final LN2 ----------------
__global__ __launch_bounds__(256) void k_ln2(float* __restrict__ out,
                                             const float* __restrict__ g2,
                                             const float* __restrict__ b2){
    __shared__ float red[8];
    int row = blockIdx.x;
    int tid = threadIdx.x;
    float x[4]; float s = 0.f;
    #pragma unroll
    for(int j=0;j<4;j++){
        int e = tid + j*256;
        x[j] = out[(size_t)row*EMB + e]; s += x[j];
    }
    float mu = blk_reduce(s, red)*(1.f/EMB);
    float q = 0.f;
    #pragma unroll
    for(int j=0;j<4;j++){ float d = x[j]-mu; q += d*d; }
    float rstd = rsqrtf(blk_reduce(q, red)*(1.f/EMB) + EPS_LN);
    #pragma unroll
    for(int j=0;j<4;j++){
        int e = tid + j*256;
        out[(size_t)row*EMB + e] = (x[j]-mu)*rstd*g2[e] + b2[e];
    }
}

// ---------------- plain fp16 warp-MMA GEMM (BK=64, SW128 swizzle) ----------------
// C[M,N] = A[M,K] @ B[N,K]^T + bias.  A, B plain fp16 row-major.
// CTA 128x128, 256 thr (8 warps 4Mx2N, warp 32x64), BK=64 (128B/row),
// SW128 XOR swizzle (no padding), 3-stage cp.async (wait 1), 2 CTAs/SM.
#define T_BYTES 16384                     // 128 rows x 128B
#define STAGE_BYTES (2*T_BYTES)           // 32768
#define GEMM_SMEM (3*STAGE_BYTES + 128)   // 98432 -> 2 CTAs/SM

template<int HALF_OUT>
__global__ __launch_bounds__(256, 2) void k_gemm_mma(
    const __half* __restrict__ A,
    const __half* __restrict__ B,
    const float* __restrict__ bias,
    float* __restrict__ Cf,
    __half* __restrict__ Cs,
    int Ka, int Nfull)
{
    extern __shared__ char smem_raw[];
    const uint32_t sb = (smem_u32(smem_raw) + 127) & ~127u;
    const int tid = threadIdx.x;
    const int wid = tid >> 5, lane = tid & 31;
    const int wm = wid & 3, wn = wid >> 2;   // 4 x 2 warp grid, warp tile 32x64

    const size_t bm = (size_t)blockIdx.y * 128;
    const size_t bn = (size_t)blockIdx.x * 128;
    const int NKC = Ka >> 6;                 // 64 real k per chunk

    const char* Ag = (const char*)(A + bm * (size_t)Ka);
    const char* Bg = (const char*)(B + bn * (size_t)Ka);
    const size_t rstride = (size_t)Ka * 2;

    const int ldr = tid >> 3;                // 0..31
    const int ldc = (tid & 7) << 4;          // 16B segment in 128B row

    auto load_stage = [&](int kc){
        uint32_t st = sb + (kc % 3)*STAGE_BYTES;
        size_t gofs = (size_t)kc*128;
        #pragma unroll
        for(int i=0;i<4;i++){
            int r = ldr + i*32;
            uint32_t dst = st + sw128((uint32_t)(r*128 + ldc));
            cp16(dst, Ag + (size_t)r*rstride + gofs + ldc);
        }
        #pragma unroll
        for(int i=0;i<4;i++){
            int r = ldr + i*32;
            uint32_t dst = st + T_BYTES + sw128((uint32_t)(r*128 + ldc));
            cp16(dst, Bg + (size_t)r*rstride + gofs + ldc);
        }
        cp_commit();
    };

    float acc[2][8][4];
    #pragma unroll
    for(int i=0;i<2;i++)
        #pragma unroll
        for(int j=0;j<8;j++)
            #pragma unroll
            for(int q=0;q<4;q++) acc[i][j][q] = 0.f;

    load_stage(0); load_stage(1);

    const uint32_t lrow = lane & 15;
    const uint32_t lcol = (lane >> 4) << 4;

    for(int kc=0; kc<NKC; kc++){
        cp_wait1();
        __syncthreads();
        if (kc+2 < NKC) load_stage(kc+2);

        uint32_t sA = sb + (kc % 3)*STAGE_BYTES;
        uint32_t sB = sA + T_BYTES;

        #pragma unroll
        for(int s=0;s<4;s++){          // four k16 steps per chunk
            uint32_t af[2][4];         // [mtile]
            uint32_t bf[4][4];         // [ntile16]
            #pragma unroll
            for(int i=0;i<2;i++){
                uint32_t off = (uint32_t)((wm*32 + i*16 + lrow)*128 + s*32 + lcol);
                ldm4(sA + sw128(off), af[i]);
            }
            #pragma unroll
            for(int j=0;j<4;j++){
                uint32_t off = (uint32_t)((wn*64 + j*16 + lrow)*128 + s*32 + lcol);
                ldm4(sB + sw128(off), bf[j]);
            }
            #pragma unroll
            for(int i=0;i<2;i++){
                #pragma unroll
                for(int j=0;j<4;j++){
                    mma16816(acc[i][2*j],   af[i], bf[j][0], bf[j][2]);
                    mma16816(acc[i][2*j+1], af[i], bf[j][1], bf[j][3]);
                }
            }
        }
    }
    cp_wait0();

    // epilogue
    const int r4 = lane >> 2, c2 = (lane & 3) << 1;
    #pragma unroll
    for(int i=0;i<2;i++){
        size_t row0 = bm + wm*32 + i*16 + r4;
        #pragma unroll
        for(int j=0;j<8;j++){
            size_t n0 = bn + wn*64 + j*8 + c2;
            float b0 = bias[n0], b1 = bias[n0+1];
            float v00 = acc[i][j][0] + b0, v01 = acc[i][j][1] + b1;
            float v10 = acc[i][j][2] + b0, v11 = acc[i][j][3] + b1;
            if (HALF_OUT){
                *(uint32_t*)(Cs + row0*(size_t)Nfull + n0) =
                    packh(__float2half_rn(v00), __float2half_rn(v01));
                *(uint32_t*)(Cs + (row0+8)*(size_t)Nfull + n0) =
                    packh(__float2half_rn(v10), __float2half_rn(v11));
            } else {
                float* d0 = Cf + row0*(size_t)Nfull + n0;
                float* d1 = Cf + (row0+8)*(size_t)Nfull + n0;
                d0[0] = v00; d0[1] = v01;
                d1[0] = v10; d1[1] = v11;
            }
        }
    }
}

// ---------------- launch ----------------
extern "C" void kernel_launch(void* const* d_in, const int* in_sizes, int n_in,
                              void* d_out, int out_size){
    const float* inp   = (const float*)d_in[0];
    const float* wq    = (const float*)d_in[1];
    const float* wk    = (const float*)d_in[2];
    const float* wv    = (const float*)d_in[3];
    const float* ln1_g = (const float*)d_in[4];
    const float* ln1_b = (const float*)d_in[5];
    const float* fc1_w = (const float*)d_in[6];
    const float* fc1_b = (const float*)d_in[7];
    const float* fc2_w = (const float*)d_in[8];
    const float* fc2_b = (const float*)d_in[9];
    const float* ln2_g = (const float*)d_in[10];
    const float* ln2_b = (const float*)d_in[11];
    float* out = (float*)d_out;

    __half *y1p=nullptr, *h1p=nullptr, *w1p=nullptr, *w2p=nullptr;
    cudaGetSymbolAddress((void**)&y1p, g_y1);
    cudaGetSymbolAddress((void**)&h1p, g_h1);
    cudaGetSymbolAddress((void**)&w1p, g_w1);
    cudaGetSymbolAddress((void**)&w2p, g_w2);

    cudaFuncSetAttribute(k_gemm_mma<1>, cudaFuncAttributeMaxDynamicSharedMemorySize, GEMM_SMEM);
    cudaFuncSetAttribute(k_gemm_mma<0>, cudaFuncAttributeMaxDynamicSharedMemorySize, GEMM_SMEM);

    // launch 1: weight fp16 cast + xsum partials + prep_M
    k_presplit<<<8705, 256>>>(inp, wq, wk, fc1_w, fc2_w, w1p, w2p);
    // launch 2
    k_diagv<<<16384+512, 256>>>(inp, wv);
    // launch 3
    k_ln1<<<NROWS, 256>>>(inp, ln1_g, ln1_b);

    // launch 4: h = y @ fc1_w^T + b1 (fp16 out) — ncu slot
    k_gemm_mma<1><<<dim3(MAPD/128, NROWS/128), 256, GEMM_SMEM>>>(
        y1p, w1p, fc1_b, nullptr, h1p, EMB, MAPD);
    // launch 5: out = h @ fc2_w^T + b2 (fp32 out)
    k_gemm_mma<0><<<dim3(EMB/128, NROWS/128), 256, GEMM_SMEM>>>(
        h1p, w2p, fc2_b, out, nullptr, MAPD, EMB);

    k_ln2<<<NROWS, 256>>>(out, ln2_g, ln2_b);
}

// round 13
// speedup vs baseline: 2.9755x; 1.0552x over previous
#include <cuda_runtime.h>
#include <cuda_bf16.h>
#include <cuda_fp16.h>
#include <cstdint>

#define CC 32
#define TT 2048
#define EMB 1024
#define NH 16
#define DH 64
#define MAPD 4096
#define NROWS (CC*TT)          // 65536
#define NVEC (NROWS*NH)        // 1048576 vectors of 64
#define EPS_LN 1e-5f

// ---------------- scratch (static device globals) ----------------
__device__ float g_M[DH*DH];
__device__ float g_xpart[512*EMB];
__device__ float g_vsum[CC*EMB];
__device__ float g_w[NROWS*NH];
// everything plain fp16 row-major
__device__ __align__(128) __half g_y1[(size_t)NROWS*EMB];      // 134 MB
__device__ __align__(128) __half g_h1[(size_t)NROWS*MAPD];     // 536 MB
__device__ __align__(128) __half g_w1[(size_t)MAPD*EMB];       // 8 MB
__device__ __align__(128) __half g_w2[(size_t)EMB*MAPD];       // 8 MB

// ---------------- helpers ----------------
__device__ __forceinline__ uint32_t smem_u32(const void* p){
    uint32_t a;
    asm("{ .reg .u64 t; cvta.to.shared.u64 t, %1; cvt.u32.u64 %0, t; }" : "=r"(a) : "l"(p));
    return a;
}
__device__ __forceinline__ void cp16(uint32_t dst, const void* src){
    asm volatile("cp.async.cg.shared.global [%0], [%1], 16;" :: "r"(dst), "l"(src) : "memory");
}
__device__ __forceinline__ void cp_commit(){ asm volatile("cp.async.commit_group;" ::: "memory"); }
__device__ __forceinline__ void cp_wait1(){ asm volatile("cp.async.wait_group 1;" ::: "memory"); }
__device__ __forceinline__ void cp_wait0(){ asm volatile("cp.async.wait_group 0;" ::: "memory"); }

__device__ __forceinline__ void ldm4(uint32_t a, uint32_t* r){
    asm volatile("ldmatrix.sync.aligned.m8n8.x4.shared.b16 {%0,%1,%2,%3}, [%4];"
        : "=r"(r[0]), "=r"(r[1]), "=r"(r[2]), "=r"(r[3]) : "r"(a));
}
__device__ __forceinline__ void mma16816(float* d, const uint32_t* a, uint32_t b0, uint32_t b1){
    asm volatile("mma.sync.aligned.m16n8k16.row.col.f32.f16.f16.f32 "
        "{%0,%1,%2,%3}, {%4,%5,%6,%7}, {%8,%9}, {%0,%1,%2,%3};"
        : "+f"(d[0]), "+f"(d[1]), "+f"(d[2]), "+f"(d[3])
        : "r"(a[0]), "r"(a[1]), "r"(a[2]), "r"(a[3]), "r"(b0), "r"(b1));
}
__device__ __forceinline__ uint32_t packh(__half a, __half b){
    return (uint32_t)(*(unsigned short*)&a) | ((uint32_t)(*(unsigned short*)&b) << 16);
}
__device__ __forceinline__ uint32_t sw128(uint32_t off){
    return off ^ ((off >> 3) & 0x70);
}

// ---------------- kernel 1: weight fp16 cast + partial xsum + prep_M ----------------
__global__ void k_presplit(const float* __restrict__ inp,
                           const float* __restrict__ wq, const float* __restrict__ wk,
                           const float* __restrict__ w1src, const float* __restrict__ w2src,
                           __half* __restrict__ d1, __half* __restrict__ d2){
    int b = blockIdx.x, tid = threadIdx.x;
    if(b < 8192){
        const float* src; __half* dst; int i;
        if(b < 4096){ src = w1src; dst = d1; i = b*256 + tid; }
        else        { src = w2src; dst = d2; i = (b-4096)*256 + tid; }
        int base = i*4;
        float4 v = *(const float4*)(src + base);
        *(uint2*)(dst + base) = make_uint2(
            packh(__float2half_rn(v.x), __float2half_rn(v.y)),
            packh(__float2half_rn(v.z), __float2half_rn(v.w)));
        return;
    }
    if(b == 8704){
        __shared__ float sq[DH*DH], sk[DH*DH];
        for(int i=tid;i<DH*DH;i+=256){ sq[i]=wq[i]; sk[i]=wk[i]; }
        __syncthreads();
        for(int idx=tid; idx<DH*DH; idx+=256){
            int d = idx/DH, e = idx%DH;
            float s = 0.f;
            #pragma unroll
            for(int o=0;o<DH;o++) s += sq[o*DH+d]*sk[o*DH+e];
            g_M[idx] = s;
        }
        return;
    }
    int b2 = b - 8192;
    int c = b2>>4, seg = b2&15;
    size_t base = ((size_t)c*TT + (size_t)seg*128)*EMB;
    #pragma unroll
    for(int j=0;j<4;j++){
        int e = tid + j*256;
        float acc = 0.f;
        const float* p = inp + base + e;
        #pragma unroll 4
        for(int t=0;t<128;t++) acc += p[(size_t)t*EMB];
        g_xpart[(size_t)b2*EMB + e] = acc;
    }
}

// ---------------- kernel 2: tensor-core diag + vsum ----------------
// blocks [0,8192): diag via mma — each block handles 128 vectors of 64.
// blocks [8192, 8704): vsum.
__global__ __launch_bounds__(256) void k_diagt(const float* __restrict__ inp,
                                               const float* __restrict__ wv){
    if(blockIdx.x >= 8192){
        int b2 = blockIdx.x - 8192;
        int c = b2>>4, h = b2&15;
        __shared__ float xs[DH];
        int tid = threadIdx.x;
        if(tid < DH){
            float s = 0.f;
            #pragma unroll
            for(int seg=0;seg<16;seg++) s += g_xpart[(size_t)(c*16+seg)*EMB + h*DH + tid];
            xs[tid] = s;
        }
        __syncthreads();
        if(tid < DH){
            float s = 0.f;
            #pragma unroll
            for(int d=0;d<DH;d++) s += xs[d]*wv[tid*DH+d];
            g_vsum[c*EMB + h*DH + tid] = s;
        }
        return;
    }
    // diag: Y = X @ M (X: 128x64 fp16 rows = head-vectors; M staged transposed)
    __shared__ __align__(128) char Xs_raw[128*128];   // 128 rows x 128B (64 fp16), sw128
    __shared__ __align__(128) char Ms_raw[64*128];    // 64 rows (e) x 128B (64 fp16 over d), sw128
    const uint32_t Xs = smem_u32(Xs_raw);
    const uint32_t Ms = smem_u32(Ms_raw);
    int tid = threadIdx.x;
    int wid = tid >> 5, lane = tid & 31;

    // stage X (cast fp32 -> fp16, swizzled)
    {
        const float* src = inp + (size_t)blockIdx.x * (128*64);
        #pragma unroll
        for(int it=0; it<8; it++){
            int i = tid + it*256;          // 0..2047 : (row, 16B-seg of 4 floats)
            int r = i >> 4, seg = i & 15;
            float4 v = *(const float4*)(src + (size_t)r*64 + seg*4);
            uint2 hv = make_uint2(
                packh(__float2half_rn(v.x), __float2half_rn(v.y)),
                packh(__float2half_rn(v.z), __float2half_rn(v.w)));
            *(uint2*)(Xs_raw + sw128((uint32_t)(r*128 + seg*8))) = hv;
        }
    }
    // stage M transposed: Ms[e][d] = M[d][e]
    #pragma unroll
    for(int it=0; it<16; it++){
        int i = tid + it*256;              // 0..4095 : d*64+e
        int d = i >> 6, e = i & 63;
        __half h = __float2half_rn(g_M[i]);
        *(__half*)(Ms_raw + sw128((uint32_t)(e*128 + d*2))) = h;
    }
    __syncthreads();

    const uint32_t lrow = lane & 15;
    const uint32_t lcol = (lane >> 4) << 4;

    // per-warp: rows wid*16 .. +15
    uint32_t af[4][4];
    float acc[8][4];
    #pragma unroll
    for(int j=0;j<8;j++)
        #pragma unroll
        for(int q=0;q<4;q++) acc[j][q] = 0.f;

    #pragma unroll
    for(int s=0;s<4;s++){
        ldm4(Xs + sw128((uint32_t)((wid*16 + lrow)*128 + s*32 + lcol)), af[s]);
        uint32_t bf[4][4];
        #pragma unroll
        for(int j=0;j<4;j++)
            ldm4(Ms + sw128((uint32_t)((j*16 + lrow)*128 + s*32 + lcol)), bf[j]);
        #pragma unroll
        for(int j=0;j<4;j++){
            mma16816(acc[2*j],   af[s], bf[j][0], bf[j][2]);
            mma16816(acc[2*j+1], af[s], bf[j][1], bf[j][3]);
        }
    }

    // diag_r = sum_e Y[r][e] * x[r][e]; A-frag and D-frag share the lane map.
    float pA = 0.f, pB = 0.f;     // rows lane/4 and lane/4+8 (within warp's m16)
    #pragma unroll
    for(int j=0;j<8;j++){
        int s = j >> 1;
        uint32_t xlo = af[s][(j&1) ? 2 : 0];   // row lane/4,   cols match acc[j][0..1]
        uint32_t xhi = af[s][(j&1) ? 3 : 1];   // row lane/4+8, cols match acc[j][2..3]
        float2 fl = __half22float2(*(__half2*)&xlo);
        float2 fh = __half22float2(*(__half2*)&xhi);
        pA += acc[j][0]*fl.x + acc[j][1]*fl.y;
        pB += acc[j][2]*fh.x + acc[j][3]*fh.y;
    }
    pA += __shfl_xor_sync(0xffffffffu, pA, 1);
    pA += __shfl_xor_sync(0xffffffffu, pA, 2);
    pB += __shfl_xor_sync(0xffffffffu, pB, 1);
    pB += __shfl_xor_sync(0xffffffffu, pB, 2);
    if((lane & 3) == 0){
        size_t base = (size_t)blockIdx.x*128 + wid*16 + (lane>>2);
        g_w[base]     = pA * (1.0f/32.0f);
        g_w[base + 8] = pB * (1.0f/32.0f);
    }
}

// ---------------- block reduction ----------------
__device__ __forceinline__ float blk_reduce(float v, float* red){
    int lane = threadIdx.x&31, w = threadIdx.x>>5;
    #pragma unroll
    for(int off=16;off;off>>=1) v += __shfl_down_sync(0xffffffffu, v, off);
    if(lane==0) red[w] = v;
    __syncthreads();
    if(w==0){
        float x = (lane<8)? red[lane] : 0.f;
        #pragma unroll
        for(int off=4;off;off>>=1) x += __shfl_down_sync(0xffffffffu, x, off);
        if(lane==0) red[0] = x;
    }
    __syncthreads();
    float r = red[0];
    __syncthreads();
    return r;
}

// ---------------- kernel 3: softmax + residual + LN1, fp16 out ----------------
__global__ __launch_bounds__(256) void k_ln1(const float* __restrict__ inp,
                                             const float* __restrict__ g1,
                                             const float* __restrict__ b1){
    __shared__ float red[8];
    __shared__ float sw[CC*NH];
    __shared__ float ws[NH];
    int row = blockIdx.x, c = row>>11, t = row&2047;
    int tid = threadIdx.x;
    #pragma unroll
    for(int i=0;i<2;i++){
        int idx = tid + i*256;
        int cc = idx >> 4, h = idx & 15;
        sw[idx] = g_w[(size_t)cc*(TT*NH) + (size_t)t*NH + h];
    }
    __syncthreads();
    if(tid < NH){
        int h = tid;
        float m = -1e30f;
        #pragma unroll
        for(int c2=0;c2<CC;c2++) m = fmaxf(m, sw[c2*NH + h]);
        float s = 0.f;
        #pragma unroll
        for(int c2=0;c2<CC;c2++) s += __expf(sw[c2*NH + h]-m);
        ws[h] = __expf(sw[c*NH + h]-m) / s;
    }
    __syncthreads();
    float x[4]; float s = 0.f;
    #pragma unroll
    for(int j=0;j<4;j++){
        int e = tid + j*256;
        float v = inp[(size_t)row*EMB + e] + ws[e>>6]*g_vsum[c*EMB + e];
        x[j] = v; s += v;
    }
    float mu = blk_reduce(s, red)*(1.f/EMB);
    float q = 0.f;
    #pragma unroll
    for(int j=0;j<4;j++){ float d = x[j]-mu; q += d*d; }
    float rstd = rsqrtf(blk_reduce(q, red)*(1.f/EMB) + EPS_LN);
    #pragma unroll
    for(int j=0;j<4;j++){
        int e = tid + j*256;
        float val = x[j] + (x[j]-mu)*rstd*g1[e] + b1[e];
        g_y1[(size_t)row*EMB + e] = __float2half_rn(val);
    }
}

// ---------------- final LN2 ----------------
__global__ __launch_bounds__(256) void k_ln2(float* __restrict__ out,
                                             const float* __restrict__ g2,
                                             const float* __restrict__ b2){
    __shared__ float red[8];
    int row = blockIdx.x;
    int tid = threadIdx.x;
    float x[4]; float s = 0.f;
    #pragma unroll
    for(int j=0;j<4;j++){
        int e = tid + j*256;
        x[j] = out[(size_t)row*EMB + e]; s += x[j];
    }
    float mu = blk_reduce(s, red)*(1.f/EMB);
    float q = 0.f;
    #pragma unroll
    for(int j=0;j<4;j++){ float d = x[j]-mu; q += d*d; }
    float rstd = rsqrtf(blk_reduce(q, red)*(1.f/EMB) + EPS_LN);
    #pragma unroll
    for(int j=0;j<4;j++){
        int e = tid + j*256;
        out[(size_t)row*EMB + e] = (x[j]-mu)*rstd*g2[e] + b2[e];
    }
}

// ---------------- plain fp16 warp-MMA GEMM (BK=64, SW128 swizzle) ----------------
#define T_BYTES 16384                     // 128 rows x 128B
#define STAGE_BYTES (2*T_BYTES)           // 32768
#define GEMM_SMEM (3*STAGE_BYTES + 128)   // 98432 -> 2 CTAs/SM

template<int HALF_OUT>
__global__ __launch_bounds__(256, 2) void k_gemm_mma(
    const __half* __restrict__ A,
    const __half* __restrict__ B,
    const float* __restrict__ bias,
    float* __restrict__ Cf,
    __half* __restrict__ Cs,
    int Ka, int Nfull)
{
    extern __shared__ char smem_raw[];
    const uint32_t sb = (smem_u32(smem_raw) + 127) & ~127u;
    const int tid = threadIdx.x;
    const int wid = tid >> 5, lane = tid & 31;
    const int wm = wid & 3, wn = wid >> 2;   // 4 x 2 warp grid, warp tile 32x64

    const size_t bm = (size_t)blockIdx.y * 128;
    const size_t bn = (size_t)blockIdx.x * 128;
    const int NKC = Ka >> 6;                 // 64 real k per chunk

    const char* Ag = (const char*)(A + bm * (size_t)Ka);
    const char* Bg = (const char*)(B + bn * (size_t)Ka);
    const size_t rstride = (size_t)Ka * 2;

    const int ldr = tid >> 3;                // 0..31
    const int ldc = (tid & 7) << 4;          // 16B segment in 128B row

    auto load_stage = [&](int kc){
        uint32_t st = sb + (kc % 3)*STAGE_BYTES;
        size_t gofs = (size_t)kc*128;
        #pragma unroll
        for(int i=0;i<4;i++){
            int r = ldr + i*32;
            uint32_t dst = st + sw128((uint32_t)(r*128 + ldc));
            cp16(dst, Ag + (size_t)r*rstride + gofs + ldc);
        }
        #pragma unroll
        for(int i=0;i<4;i++){
            int r = ldr + i*32;
            uint32_t dst = st + T_BYTES + sw128((uint32_t)(r*128 + ldc));
            cp16(dst, Bg + (size_t)r*rstride + gofs + ldc);
        }
        cp_commit();
    };

    float acc[2][8][4];
    #pragma unroll
    for(int i=0;i<2;i++)
        #pragma unroll
        for(int j=0;j<8;j++)
            #pragma unroll
            for(int q=0;q<4;q++) acc[i][j][q] = 0.f;

    load_stage(0); load_stage(1);

    const uint32_t lrow = lane & 15;
    const uint32_t lcol = (lane >> 4) << 4;

    for(int kc=0; kc<NKC; kc++){
        cp_wait1();
        __syncthreads();
        if (kc+2 < NKC) load_stage(kc+2);

        uint32_t sA = sb + (kc % 3)*STAGE_BYTES;
        uint32_t sB = sA + T_BYTES;

        #pragma unroll
        for(int s=0;s<4;s++){          // four k16 steps per chunk
            uint32_t af[2][4];         // [mtile]
            uint32_t bf[4][4];         // [ntile16]
            #pragma unroll
            for(int i=0;i<2;i++){
                uint32_t off = (uint32_t)((wm*32 + i*16 + lrow)*128 + s*32 + lcol);
                ldm4(sA + sw128(off), af[i]);
            }
            #pragma unroll
            for(int j=0;j<4;j++){
                uint32_t off = (uint32_t)((wn*64 + j*16 + lrow)*128 + s*32 + lcol);
                ldm4(sB + sw128(off), bf[j]);
            }
            #pragma unroll
            for(int i=0;i<2;i++){
                #pragma unroll
                for(int j=0;j<4;j++){
                    mma16816(acc[i][2*j],   af[i], bf[j][0], bf[j][2]);
                    mma16816(acc[i][2*j+1], af[i], bf[j][1], bf[j][3]);
                }
            }
        }
    }
    cp_wait0();

    // epilogue
    const int r4 = lane >> 2, c2 = (lane & 3) << 1;
    #pragma unroll
    for(int i=0;i<2;i++){
        size_t row0 = bm + wm*32 + i*16 + r4;
        #pragma unroll
        for(int j=0;j<8;j++){
            size_t n0 = bn + wn*64 + j*8 + c2;
            float b0 = bias[n0], b1 = bias[n0+1];
            float v00 = acc[i][j][0] + b0, v01 = acc[i][j][1] + b1;
            float v10 = acc[i][j][2] + b0, v11 = acc[i][j][3] + b1;
            if (HALF_OUT){
                *(uint32_t*)(Cs + row0*(size_t)Nfull + n0) =
                    packh(__float2half_rn(v00), __float2half_rn(v01));
                *(uint32_t*)(Cs + (row0+8)*(size_t)Nfull + n0) =
                    packh(__float2half_rn(v10), __float2half_rn(v11));
            } else {
                float* d0 = Cf + row0*(size_t)Nfull + n0;
                float* d1 = Cf + (row0+8)*(size_t)Nfull + n0;
                d0[0] = v00; d0[1] = v01;
                d1[0] = v10; d1[1] = v11;
            }
        }
    }
}

// ---------------- launch ----------------
extern "C" void kernel_launch(void* const* d_in, const int* in_sizes, int n_in,
                              void* d_out, int out_size){
    const float* inp   = (const float*)d_in[0];
    const float* wq    = (const float*)d_in[1];
    const float* wk    = (const float*)d_in[2];
    const float* wv    = (const float*)d_in[3];
    const float* ln1_g = (const float*)d_in[4];
    const float* ln1_b = (const float*)d_in[5];
    const float* fc1_w = (const float*)d_in[6];
    const float* fc1_b = (const float*)d_in[7];
    const float* fc2_w = (const float*)d_in[8];
    const float* fc2_b = (const float*)d_in[9];
    const float* ln2_g = (const float*)d_in[10];
    const float* ln2_b = (const float*)d_in[11];
    float* out = (float*)d_out;

    __half *y1p=nullptr, *h1p=nullptr, *w1p=nullptr, *w2p=nullptr;
    cudaGetSymbolAddress((void**)&y1p, g_y1);
    cudaGetSymbolAddress((void**)&h1p, g_h1);
    cudaGetSymbolAddress((void**)&w1p, g_w1);
    cudaGetSymbolAddress((void**)&w2p, g_w2);

    cudaFuncSetAttribute(k_gemm_mma<1>, cudaFuncAttributeMaxDynamicSharedMemorySize, GEMM_SMEM);
    cudaFuncSetAttribute(k_gemm_mma<0>, cudaFuncAttributeMaxDynamicSharedMemorySize, GEMM_SMEM);

    // launch 1: weight fp16 cast + xsum partials + prep_M
    k_presplit<<<8705, 256>>>(inp, wq, wk, fc1_w, fc2_w, w1p, w2p);
    // launch 2: tensor-core diag + vsum
    k_diagt<<<8192+512, 256>>>(inp, wv);
    // launch 3
    k_ln1<<<NROWS, 256>>>(inp, ln1_g, ln1_b);

    // launch 4: h = y @ fc1_w^T + b1 (fp16 out) — ncu slot
    k_gemm_mma<1><<<dim3(MAPD/128, NROWS/128), 256, GEMM_SMEM>>>(
        y1p, w1p, fc1_b, nullptr, h1p, EMB, MAPD);
    // launch 5: out = h @ fc2_w^T + b2 (fp32 out)
    k_gemm_mma<0><<<dim3(EMB/128, NROWS/128), 256, GEMM_SMEM>>>(
        h1p, w2p, fc2_b, out, nullptr, MAPD, EMB);

    k_ln2<<<NROWS, 256>>>(out, ln2_g, ln2_b);
}